// round 1
// baseline (speedup 1.0000x reference)
#include <cuda_runtime.h>

#define B_  2
#define L_  2048
#define D_  1024
#define H_  16
#define HD_ 64
#define M_  (B_ * L_)   // 4096 rows for the projection GEMMs

// Scratch (device globals: allowed; no runtime allocation)
__device__ float g_q[B_ * H_ * L_ * HD_];   // [B,H,L,HD]
__device__ float g_k[B_ * H_ * L_ * HD_];
__device__ float g_v[B_ * H_ * L_ * HD_];
__device__ float g_x[M_ * D_];              // [B,L,D] combined heads before O proj

// ---------------------------------------------------------------------------
// Projection GEMM: C[M_,1024] = X[M_,1024] @ W[1024,1024] + b
// mode 0/1/2: write head-split into g_q/g_k/g_v ; mode 3: row-major into Yout
// xsel 0: X = Xin ; xsel 1: X = g_x
// 64x64 block tile, Ktile=16, 16x16 threads, 4x4 per thread.
// ---------------------------------------------------------------------------
__global__ void proj_kernel(const float* __restrict__ Xin,
                            const float* __restrict__ W,
                            const float* __restrict__ bias,
                            float* __restrict__ Yout,
                            int xsel, int mode)
{
    __shared__ float As[64][17];
    __shared__ float Bs[16][68];

    const float* X = xsel ? g_x : Xin;
    int tx = threadIdx.x, ty = threadIdx.y;
    int tid = ty * 16 + tx;
    int m0 = blockIdx.y * 64;
    int n0 = blockIdx.x * 64;

    float acc[4][4] = {};

    for (int k0 = 0; k0 < D_; k0 += 16) {
        // A tile: 64 x 16
        {
            int row = tid >> 2;
            int c4  = (tid & 3) * 4;
            float4 v = *(const float4*)(X + (size_t)(m0 + row) * D_ + k0 + c4);
            As[row][c4+0] = v.x; As[row][c4+1] = v.y;
            As[row][c4+2] = v.z; As[row][c4+3] = v.w;
        }
        // B tile: 16 x 64
        {
            int row = tid >> 4;
            int c4  = (tid & 15) * 4;
            float4 v = *(const float4*)(W + (size_t)(k0 + row) * D_ + n0 + c4);
            Bs[row][c4+0] = v.x; Bs[row][c4+1] = v.y;
            Bs[row][c4+2] = v.z; Bs[row][c4+3] = v.w;
        }
        __syncthreads();
        #pragma unroll
        for (int kk = 0; kk < 16; kk++) {
            float a[4], b[4];
            #pragma unroll
            for (int i = 0; i < 4; i++) a[i] = As[ty * 4 + i][kk];
            #pragma unroll
            for (int j = 0; j < 4; j++) b[j] = Bs[kk][tx * 4 + j];
            #pragma unroll
            for (int i = 0; i < 4; i++)
                #pragma unroll
                for (int j = 0; j < 4; j++)
                    acc[i][j] = fmaf(a[i], b[j], acc[i][j]);
        }
        __syncthreads();
    }

    float* dst = (mode == 0) ? g_q : (mode == 1) ? g_k : (mode == 2) ? g_v : Yout;

    #pragma unroll
    for (int i = 0; i < 4; i++) {
        int r = m0 + ty * 4 + i;
        #pragma unroll
        for (int j = 0; j < 4; j++) {
            int c = n0 + tx * 4 + j;
            float v = acc[i][j] + bias[c];
            if (mode < 3) {
                int b  = r / L_, l = r % L_;
                int h  = c / HD_, hd = c % HD_;
                dst[(((size_t)(b * H_ + h)) * L_ + l) * HD_ + hd] = v;
            } else {
                dst[(size_t)r * D_ + c] = v;
            }
        }
    }
}

// ---------------------------------------------------------------------------
// Logits: for each (b,h): attn[q,k] = 0.125 * dot(Q[q,:],K[k,:]) + bias[b,q,k]
// K dim = 64 fully resident. 64x64 tile, 16x16 threads, 4x4 per thread.
// ---------------------------------------------------------------------------
__global__ void logits_kernel(const float* __restrict__ abias,
                              float* __restrict__ attn)
{
    __shared__ float Qs[64][65];
    __shared__ float Ks[64][65];

    int bh = blockIdx.z;
    int q0 = blockIdx.y * 64;
    int k0 = blockIdx.x * 64;
    int tx = threadIdx.x, ty = threadIdx.y;
    int tid = ty * 16 + tx;

    const float* Q = g_q + (size_t)bh * L_ * HD_;
    const float* K = g_k + (size_t)bh * L_ * HD_;

    for (int i = tid; i < 64 * 16; i += 256) {
        int row = i >> 4;
        int c4  = (i & 15) * 4;
        float4 q4 = *(const float4*)(Q + (size_t)(q0 + row) * HD_ + c4);
        Qs[row][c4+0] = q4.x; Qs[row][c4+1] = q4.y;
        Qs[row][c4+2] = q4.z; Qs[row][c4+3] = q4.w;
        float4 k4 = *(const float4*)(K + (size_t)(k0 + row) * HD_ + c4);
        Ks[row][c4+0] = k4.x; Ks[row][c4+1] = k4.y;
        Ks[row][c4+2] = k4.z; Ks[row][c4+3] = k4.w;
    }
    __syncthreads();

    float acc[4][4] = {};
    #pragma unroll 8
    for (int kk = 0; kk < 64; kk++) {
        float a[4], b[4];
        #pragma unroll
        for (int i = 0; i < 4; i++) a[i] = Qs[ty * 4 + i][kk];
        #pragma unroll
        for (int j = 0; j < 4; j++) b[j] = Ks[tx * 4 + j][kk];
        #pragma unroll
        for (int i = 0; i < 4; i++)
            #pragma unroll
            for (int j = 0; j < 4; j++)
                acc[i][j] = fmaf(a[i], b[j], acc[i][j]);
    }

    int b = bh >> 4;  // / H_
    size_t base = (size_t)bh * L_ * L_;
    #pragma unroll
    for (int i = 0; i < 4; i++) {
        int q = q0 + ty * 4 + i;
        #pragma unroll
        for (int j = 0; j < 4; j++) {
            int k = k0 + tx * 4 + j;
            attn[base + (size_t)q * L_ + k] =
                acc[i][j] * 0.125f + abias[((size_t)b * L_ + q) * L_ + k];
        }
    }
}

// ---------------------------------------------------------------------------
// Row softmax over last dim (L_=2048), in place. One block per row.
// ---------------------------------------------------------------------------
__global__ void softmax_kernel(float* __restrict__ attn)
{
    size_t row = blockIdx.x;
    float* p = attn + row * L_;
    int tid = threadIdx.x;       // 256 threads, 8 elems each
    int ln = tid & 31, wid = tid >> 5;

    float v[8];
    #pragma unroll
    for (int i = 0; i < 2; i++) {
        float4 t = *(const float4*)(p + tid * 8 + i * 4);
        v[i*4+0] = t.x; v[i*4+1] = t.y; v[i*4+2] = t.z; v[i*4+3] = t.w;
    }

    __shared__ float sm[16];

    float m = v[0];
    #pragma unroll
    for (int i = 1; i < 8; i++) m = fmaxf(m, v[i]);
    #pragma unroll
    for (int o = 16; o > 0; o >>= 1) m = fmaxf(m, __shfl_xor_sync(~0u, m, o));
    if (ln == 0) sm[wid] = m;
    __syncthreads();
    m = sm[0];
    #pragma unroll
    for (int k = 1; k < 8; k++) m = fmaxf(m, sm[k]);

    float s = 0.f;
    #pragma unroll
    for (int i = 0; i < 8; i++) { v[i] = __expf(v[i] - m); s += v[i]; }
    #pragma unroll
    for (int o = 16; o > 0; o >>= 1) s += __shfl_xor_sync(~0u, s, o);
    if (ln == 0) sm[8 + wid] = s;
    __syncthreads();
    s = 0.f;
    #pragma unroll
    for (int k = 0; k < 8; k++) s += sm[8 + k];

    float inv = 1.0f / s;
    #pragma unroll
    for (int i = 0; i < 2; i++) {
        float4 t;
        t.x = v[i*4+0] * inv; t.y = v[i*4+1] * inv;
        t.z = v[i*4+2] * inv; t.w = v[i*4+3] * inv;
        *(float4*)(p + tid * 8 + i * 4) = t;
    }
}

// ---------------------------------------------------------------------------
// x = attn @ V per (b,h): [L_,L_] x [L_,64] -> write combined heads into g_x
// Block: 64 q-rows x 64 cols (full HD), Ktile=16.
// ---------------------------------------------------------------------------
__global__ void av_kernel(const float* __restrict__ attn)
{
    __shared__ float As[64][17];
    __shared__ float Vs[16][68];

    int bh = blockIdx.y;
    int q0 = blockIdx.x * 64;
    int tx = threadIdx.x, ty = threadIdx.y;
    int tid = ty * 16 + tx;

    const float* A = attn + (size_t)bh * L_ * L_;
    const float* V = g_v + (size_t)bh * L_ * HD_;

    float acc[4][4] = {};

    for (int k0 = 0; k0 < L_; k0 += 16) {
        {
            int row = tid >> 2;
            int c4  = (tid & 3) * 4;
            float4 v = *(const float4*)(A + (size_t)(q0 + row) * L_ + k0 + c4);
            As[row][c4+0] = v.x; As[row][c4+1] = v.y;
            As[row][c4+2] = v.z; As[row][c4+3] = v.w;
        }
        {
            int row = tid >> 4;
            int c4  = (tid & 15) * 4;
            float4 v = *(const float4*)(V + (size_t)(k0 + row) * HD_ + c4);
            Vs[row][c4+0] = v.x; Vs[row][c4+1] = v.y;
            Vs[row][c4+2] = v.z; Vs[row][c4+3] = v.w;
        }
        __syncthreads();
        #pragma unroll
        for (int kk = 0; kk < 16; kk++) {
            float a[4], b[4];
            #pragma unroll
            for (int i = 0; i < 4; i++) a[i] = As[ty * 4 + i][kk];
            #pragma unroll
            for (int j = 0; j < 4; j++) b[j] = Vs[kk][tx * 4 + j];
            #pragma unroll
            for (int i = 0; i < 4; i++)
                #pragma unroll
                for (int j = 0; j < 4; j++)
                    acc[i][j] = fmaf(a[i], b[j], acc[i][j]);
        }
        __syncthreads();
    }

    int b = bh >> 4;       // / H_
    int h = bh & 15;       // % H_
    #pragma unroll
    for (int i = 0; i < 4; i++) {
        int q = q0 + ty * 4 + i;
        #pragma unroll
        for (int j = 0; j < 4; j++) {
            int hd = tx * 4 + j;
            g_x[((size_t)(b * L_ + q)) * D_ + h * HD_ + hd] = acc[i][j];
        }
    }
}

// ---------------------------------------------------------------------------
extern "C" void kernel_launch(void* const* d_in, const int* in_sizes, int n_in,
                              void* d_out, int out_size)
{
    const float* query = (const float*)d_in[0];
    const float* abias = (const float*)d_in[1];
    const float* Wq    = (const float*)d_in[2];
    const float* bq    = (const float*)d_in[3];
    const float* Wk    = (const float*)d_in[4];
    const float* bk    = (const float*)d_in[5];
    const float* Wv    = (const float*)d_in[6];
    const float* bv    = (const float*)d_in[7];
    const float* Wo    = (const float*)d_in[8];
    const float* bo    = (const float*)d_in[9];

    float* out  = (float*)d_out;
    float* ans  = out;                              // [B,L,D]
    float* attn = out + (size_t)M_ * D_;            // [B,H,L,L]

    dim3 blk(16, 16);
    dim3 gproj(D_ / 64, M_ / 64);

    proj_kernel<<<gproj, blk>>>(query, Wq, bq, nullptr, 0, 0);
    proj_kernel<<<gproj, blk>>>(query, Wk, bk, nullptr, 0, 1);
    proj_kernel<<<gproj, blk>>>(query, Wv, bv, nullptr, 0, 2);

    logits_kernel<<<dim3(L_ / 64, L_ / 64, B_ * H_), blk>>>(abias, attn);

    softmax_kernel<<<B_ * H_ * L_, 256>>>(attn);

    av_kernel<<<dim3(L_ / 64, B_ * H_), blk>>>(attn);

    proj_kernel<<<gproj, blk>>>(nullptr, Wo, bo, ans, 1, 3);
}

// round 4
// speedup vs baseline: 1.3119x; 1.3119x over previous
#include <cuda_runtime.h>
#include <cuda_bf16.h>
#include <cstdint>

#define B_  2
#define L_  2048
#define D_  1024
#define H_  16
#define HD_ 64
#define M_  (B_ * L_)   // 4096 rows for the projection GEMMs

// ---------------------------------------------------------------------------
// Scratch (device globals: allowed; no runtime allocation)
// Q/K stored as bf16 hi/lo split pairs (head-split layout [B,H,L,HD])
// ---------------------------------------------------------------------------
__device__ __nv_bfloat16 g_qh[B_ * H_ * L_ * HD_];
__device__ __nv_bfloat16 g_ql[B_ * H_ * L_ * HD_];
__device__ __nv_bfloat16 g_kh[B_ * H_ * L_ * HD_];
__device__ __nv_bfloat16 g_kl[B_ * H_ * L_ * HD_];
__device__ float g_v[B_ * H_ * L_ * HD_];   // [B,H,L,HD] fp32
__device__ float g_x[M_ * D_];              // [B,L,D] combined heads before O proj

__device__ __forceinline__ uint32_t smem_u32(const void* p) {
    uint32_t a;
    asm("{ .reg .u64 t; cvta.to.shared.u64 t, %1; cvt.u32.u64 %0, t; }"
        : "=r"(a) : "l"(p));
    return a;
}

// ---------------------------------------------------------------------------
// Projection GEMM: C[M_,1024] = X[M_,1024] @ W[1024,1024] + b
// mode 0: -> g_qh/g_ql (bf16 hi/lo split, head-split layout)
// mode 1: -> g_kh/g_kl
// mode 2: -> g_v  (fp32, head-split)
// mode 3: -> Yout (fp32, row-major)
// ---------------------------------------------------------------------------
__global__ void proj_kernel(const float* __restrict__ Xin,
                            const float* __restrict__ W,
                            const float* __restrict__ bias,
                            float* __restrict__ Yout,
                            int xsel, int mode)
{
    __shared__ float As[64][17];
    __shared__ float Bs[16][68];

    const float* X = xsel ? g_x : Xin;
    int tx = threadIdx.x, ty = threadIdx.y;
    int tid = ty * 16 + tx;
    int m0 = blockIdx.y * 64;
    int n0 = blockIdx.x * 64;

    float acc[4][4] = {};

    for (int k0 = 0; k0 < D_; k0 += 16) {
        {
            int row = tid >> 2;
            int c4  = (tid & 3) * 4;
            float4 v = *(const float4*)(X + (size_t)(m0 + row) * D_ + k0 + c4);
            As[row][c4+0] = v.x; As[row][c4+1] = v.y;
            As[row][c4+2] = v.z; As[row][c4+3] = v.w;
        }
        {
            int row = tid >> 4;
            int c4  = (tid & 15) * 4;
            float4 v = *(const float4*)(W + (size_t)(k0 + row) * D_ + n0 + c4);
            Bs[row][c4+0] = v.x; Bs[row][c4+1] = v.y;
            Bs[row][c4+2] = v.z; Bs[row][c4+3] = v.w;
        }
        __syncthreads();
        #pragma unroll
        for (int kk = 0; kk < 16; kk++) {
            float a[4], b[4];
            #pragma unroll
            for (int i = 0; i < 4; i++) a[i] = As[ty * 4 + i][kk];
            #pragma unroll
            for (int j = 0; j < 4; j++) b[j] = Bs[kk][tx * 4 + j];
            #pragma unroll
            for (int i = 0; i < 4; i++)
                #pragma unroll
                for (int j = 0; j < 4; j++)
                    acc[i][j] = fmaf(a[i], b[j], acc[i][j]);
        }
        __syncthreads();
    }

    #pragma unroll
    for (int i = 0; i < 4; i++) {
        int r = m0 + ty * 4 + i;
        #pragma unroll
        for (int j = 0; j < 4; j++) {
            int c = n0 + tx * 4 + j;
            float v = acc[i][j] + bias[c];
            if (mode <= 1) {
                int b  = r / L_, l = r % L_;
                int h  = c / HD_, hd = c % HD_;
                size_t idx = (((size_t)(b * H_ + h)) * L_ + l) * HD_ + hd;
                __nv_bfloat16 hi = __float2bfloat16(v);
                float rem = v - __bfloat162float(hi);
                __nv_bfloat16 lo = __float2bfloat16(rem);
                if (mode == 0) { g_qh[idx] = hi; g_ql[idx] = lo; }
                else           { g_kh[idx] = hi; g_kl[idx] = lo; }
            } else if (mode == 2) {
                int b  = r / L_, l = r % L_;
                int h  = c / HD_, hd = c % HD_;
                g_v[(((size_t)(b * H_ + h)) * L_ + l) * HD_ + hd] = v;
            } else {
                Yout[(size_t)r * D_ + c] = v;
            }
        }
    }
}

// ---------------------------------------------------------------------------
// Logits via mma.sync bf16x3 split:
//   D = Qhi*Khi^T + Qhi*Klo^T + Qlo*Khi^T  (fp32 accum)
//   attn = D * 0.125 + bias
// 128x128 tile per 256-thread CTA; 8 warps (2m x 4n), 64x32 per warp.
// SMEM: 4 tiles of [128 rows][64 bf16] = 16KB each, XOR-swizzled for ldmatrix.
// ---------------------------------------------------------------------------
#define LG_TILE   16384
#define LG_SMEM   (4 * LG_TILE + 1024)

__device__ __forceinline__ uint32_t sw128(uint32_t off) {
    return off ^ ((off >> 3) & 0x70);
}

__global__ void __launch_bounds__(256)
logits_mma(const float* __restrict__ abias, float* __restrict__ attn)
{
    extern __shared__ char smem_raw[];
    uint32_t raw = smem_u32(smem_raw);
    uint32_t base = (raw + 1023u) & ~1023u;
    char* smem = smem_raw + (base - raw);

    int tid  = threadIdx.x;
    int wid  = tid >> 5;
    int lane = tid & 31;
    int bh = blockIdx.z;
    int q0 = blockIdx.y * 128;
    int k0 = blockIdx.x * 128;

    // Stage 4 tiles: Qh, Ql, Kh, Kl — each 128 rows x 128B, contiguous in gmem.
    const char* srcs[4] = {
        (const char*)(g_qh + ((size_t)bh * L_ + q0) * HD_),
        (const char*)(g_ql + ((size_t)bh * L_ + q0) * HD_),
        (const char*)(g_kh + ((size_t)bh * L_ + k0) * HD_),
        (const char*)(g_kl + ((size_t)bh * L_ + k0) * HD_)
    };
    #pragma unroll
    for (int t = 0; t < 4; t++) {
        char* dst = smem + t * LG_TILE;
        const char* s = srcs[t];
        #pragma unroll
        for (int u = 0; u < 4; u++) {
            uint32_t off = (uint32_t)(tid + u * 256) * 16u;
            *(uint4*)(dst + sw128(off)) = *(const uint4*)(s + off);
        }
    }
    __syncthreads();

    int wm = wid >> 2;      // 0..1 : q-offset wm*64
    int wn = wid & 3;       // 0..3 : k-offset wn*32

    float acc[4][4][4] = {};   // [mfrag][nfrag][4]

    // ldmatrix base addresses (per-lane row/col components)
    int a_row_l = lane & 15;           // within 16-row frag
    int a_cb_l  = (lane >> 4) << 4;    // 0 or 16 bytes (8 bf16)
    int b_row_l = lane & 7;
    int b_cb_l  = ((lane >> 3) & 1) << 4;

    #pragma unroll
    for (int pass = 0; pass < 3; pass++) {
        uint32_t aBase = base + ((pass == 2) ? LG_TILE : 0);            // Ql : Qh
        uint32_t bBase = base + ((pass == 1) ? 3 * LG_TILE : 2 * LG_TILE); // Kl : Kh

        #pragma unroll
        for (int ks = 0; ks < 4; ks++) {
            uint32_t a[4][4];
            #pragma unroll
            for (int mf = 0; mf < 4; mf++) {
                int row = wm * 64 + mf * 16 + a_row_l;
                uint32_t off = (uint32_t)(row * 128 + ks * 32 + a_cb_l);
                uint32_t addr = aBase + sw128(off);
                asm volatile(
                    "ldmatrix.sync.aligned.m8n8.x4.shared.b16 {%0,%1,%2,%3}, [%4];"
                    : "=r"(a[mf][0]), "=r"(a[mf][1]), "=r"(a[mf][2]), "=r"(a[mf][3])
                    : "r"(addr));
            }
            uint32_t b[4][2];
            #pragma unroll
            for (int nf = 0; nf < 4; nf++) {
                int row = wn * 32 + nf * 8 + b_row_l;
                uint32_t off = (uint32_t)(row * 128 + ks * 32 + b_cb_l);
                uint32_t addr = bBase + sw128(off);
                asm volatile(
                    "ldmatrix.sync.aligned.m8n8.x2.shared.b16 {%0,%1}, [%2];"
                    : "=r"(b[nf][0]), "=r"(b[nf][1])
                    : "r"(addr));
            }
            #pragma unroll
            for (int mf = 0; mf < 4; mf++)
                #pragma unroll
                for (int nf = 0; nf < 4; nf++) {
                    asm volatile(
                        "mma.sync.aligned.m16n8k16.row.col.f32.bf16.bf16.f32 "
                        "{%0,%1,%2,%3}, {%4,%5,%6,%7}, {%8,%9}, {%0,%1,%2,%3};"
                        : "+f"(acc[mf][nf][0]), "+f"(acc[mf][nf][1]),
                          "+f"(acc[mf][nf][2]), "+f"(acc[mf][nf][3])
                        : "r"(a[mf][0]), "r"(a[mf][1]), "r"(a[mf][2]), "r"(a[mf][3]),
                          "r"(b[nf][0]), "r"(b[nf][1]));
                }
        }
    }

    // Epilogue: scale + bias, write to attn.
    int b = bh >> 4;
    size_t attn_base = (size_t)bh * L_ * L_;
    int qbase = q0 + wm * 64;
    int kbase = k0 + wn * 32;
    int r0 = lane >> 2;
    int c0 = (lane & 3) * 2;

    #pragma unroll
    for (int mf = 0; mf < 4; mf++) {
        #pragma unroll
        for (int e2 = 0; e2 < 2; e2++) {
            int q = qbase + mf * 16 + r0 + e2 * 8;
            const float* brow = abias + ((size_t)b * L_ + q) * L_;
            float* orow = attn + attn_base + (size_t)q * L_;
            #pragma unroll
            for (int nf = 0; nf < 4; nf++) {
                int k = kbase + nf * 8 + c0;
                float2 bb = *(const float2*)(brow + k);
                float2 o;
                o.x = acc[mf][nf][e2 * 2 + 0] * 0.125f + bb.x;
                o.y = acc[mf][nf][e2 * 2 + 1] * 0.125f + bb.y;
                *(float2*)(orow + k) = o;
            }
        }
    }
}

// ---------------------------------------------------------------------------
// Row softmax over last dim (L_=2048), in place. One block per row.
// ---------------------------------------------------------------------------
__global__ void softmax_kernel(float* __restrict__ attn)
{
    size_t row = blockIdx.x;
    float* p = attn + row * L_;
    int tid = threadIdx.x;       // 256 threads, 8 elems each
    int ln = tid & 31, wid = tid >> 5;

    float v[8];
    #pragma unroll
    for (int i = 0; i < 2; i++) {
        float4 t = *(const float4*)(p + tid * 8 + i * 4);
        v[i*4+0] = t.x; v[i*4+1] = t.y; v[i*4+2] = t.z; v[i*4+3] = t.w;
    }

    __shared__ float sm[16];

    float m = v[0];
    #pragma unroll
    for (int i = 1; i < 8; i++) m = fmaxf(m, v[i]);
    #pragma unroll
    for (int o = 16; o > 0; o >>= 1) m = fmaxf(m, __shfl_xor_sync(~0u, m, o));
    if (ln == 0) sm[wid] = m;
    __syncthreads();
    m = sm[0];
    #pragma unroll
    for (int k = 1; k < 8; k++) m = fmaxf(m, sm[k]);

    float s = 0.f;
    #pragma unroll
    for (int i = 0; i < 8; i++) { v[i] = __expf(v[i] - m); s += v[i]; }
    #pragma unroll
    for (int o = 16; o > 0; o >>= 1) s += __shfl_xor_sync(~0u, s, o);
    if (ln == 0) sm[8 + wid] = s;
    __syncthreads();
    s = 0.f;
    #pragma unroll
    for (int k = 0; k < 8; k++) s += sm[8 + k];

    float inv = 1.0f / s;
    #pragma unroll
    for (int i = 0; i < 2; i++) {
        float4 t;
        t.x = v[i*4+0] * inv; t.y = v[i*4+1] * inv;
        t.z = v[i*4+2] * inv; t.w = v[i*4+3] * inv;
        *(float4*)(p + tid * 8 + i * 4) = t;
    }
}

// ---------------------------------------------------------------------------
// x = attn @ V per (b,h): [L_,L_] x [L_,64] -> write combined heads into g_x
// ---------------------------------------------------------------------------
__global__ void av_kernel(const float* __restrict__ attn)
{
    __shared__ float As[64][17];
    __shared__ float Vs[16][68];

    int bh = blockIdx.y;
    int q0 = blockIdx.x * 64;
    int tx = threadIdx.x, ty = threadIdx.y;
    int tid = ty * 16 + tx;

    const float* A = attn + (size_t)bh * L_ * L_;
    const float* V = g_v + (size_t)bh * L_ * HD_;

    float acc[4][4] = {};

    for (int k0 = 0; k0 < L_; k0 += 16) {
        {
            int row = tid >> 2;
            int c4  = (tid & 3) * 4;
            float4 v = *(const float4*)(A + (size_t)(q0 + row) * L_ + k0 + c4);
            As[row][c4+0] = v.x; As[row][c4+1] = v.y;
            As[row][c4+2] = v.z; As[row][c4+3] = v.w;
        }
        {
            int row = tid >> 4;
            int c4  = (tid & 15) * 4;
            float4 v = *(const float4*)(V + (size_t)(k0 + row) * HD_ + c4);
            Vs[row][c4+0] = v.x; Vs[row][c4+1] = v.y;
            Vs[row][c4+2] = v.z; Vs[row][c4+3] = v.w;
        }
        __syncthreads();
        #pragma unroll
        for (int kk = 0; kk < 16; kk++) {
            float a[4], b[4];
            #pragma unroll
            for (int i = 0; i < 4; i++) a[i] = As[ty * 4 + i][kk];
            #pragma unroll
            for (int j = 0; j < 4; j++) b[j] = Vs[kk][tx * 4 + j];
            #pragma unroll
            for (int i = 0; i < 4; i++)
                #pragma unroll
                for (int j = 0; j < 4; j++)
                    acc[i][j] = fmaf(a[i], b[j], acc[i][j]);
        }
        __syncthreads();
    }

    int b = bh >> 4;
    int h = bh & 15;
    #pragma unroll
    for (int i = 0; i < 4; i++) {
        int q = q0 + ty * 4 + i;
        #pragma unroll
        for (int j = 0; j < 4; j++) {
            int hd = tx * 4 + j;
            g_x[((size_t)(b * L_ + q)) * D_ + h * HD_ + hd] = acc[i][j];
        }
    }
}

// ---------------------------------------------------------------------------
extern "C" void kernel_launch(void* const* d_in, const int* in_sizes, int n_in,
                              void* d_out, int out_size)
{
    const float* query = (const float*)d_in[0];
    const float* abias = (const float*)d_in[1];
    const float* Wq    = (const float*)d_in[2];
    const float* bq    = (const float*)d_in[3];
    const float* Wk    = (const float*)d_in[4];
    const float* bk    = (const float*)d_in[5];
    const float* Wv    = (const float*)d_in[6];
    const float* bv    = (const float*)d_in[7];
    const float* Wo    = (const float*)d_in[8];
    const float* bo    = (const float*)d_in[9];

    float* out  = (float*)d_out;
    float* ans  = out;                              // [B,L,D]
    float* attn = out + (size_t)M_ * D_;            // [B,H,L,L]

    cudaFuncSetAttribute(logits_mma,
                         cudaFuncAttributeMaxDynamicSharedMemorySize,
                         LG_SMEM);

    dim3 blk(16, 16);
    dim3 gproj(D_ / 64, M_ / 64);

    proj_kernel<<<gproj, blk>>>(query, Wq, bq, nullptr, 0, 0);
    proj_kernel<<<gproj, blk>>>(query, Wk, bk, nullptr, 0, 1);
    proj_kernel<<<gproj, blk>>>(query, Wv, bv, nullptr, 0, 2);

    logits_mma<<<dim3(L_ / 128, L_ / 128, B_ * H_), 256, LG_SMEM>>>(abias, attn);

    softmax_kernel<<<B_ * H_ * L_, 256>>>(attn);

    av_kernel<<<dim3(L_ / 64, B_ * H_), blk>>>(attn);

    proj_kernel<<<gproj, blk>>>(nullptr, Wo, bo, ans, 1, 3);
}

// round 5
// speedup vs baseline: 1.9119x; 1.4574x over previous
#include <cuda_runtime.h>
#include <cuda_bf16.h>
#include <cstdint>

#define B_  2
#define L_  2048
#define D_  1024
#define H_  16
#define HD_ 64
#define M_  (B_ * L_)   // 4096 rows for the projection GEMMs

// ---------------------------------------------------------------------------
// Scratch (device globals)
// ---------------------------------------------------------------------------
__device__ __nv_bfloat16 g_inh[M_ * D_], g_inl[M_ * D_];      // split query
__device__ __nv_bfloat16 g_wth[4][D_ * D_], g_wtl[4][D_ * D_]; // split W^T [n][k]
__device__ __nv_bfloat16 g_qh[B_ * H_ * L_ * HD_], g_ql[B_ * H_ * L_ * HD_];
__device__ __nv_bfloat16 g_kh[B_ * H_ * L_ * HD_], g_kl[B_ * H_ * L_ * HD_];
__device__ __nv_bfloat16 g_vh[B_ * H_ * L_ * HD_], g_vl[B_ * H_ * L_ * HD_];
__device__ __nv_bfloat16 g_xh[M_ * D_], g_xl[M_ * D_];        // split attn@V out

__device__ __forceinline__ uint32_t smem_u32(const void* p) {
    uint32_t a;
    asm("{ .reg .u64 t; cvta.to.shared.u64 t, %1; cvt.u32.u64 %0, t; }"
        : "=r"(a) : "l"(p));
    return a;
}

__device__ __forceinline__ uint32_t sw128(uint32_t off) {
    return off ^ ((off >> 3) & 0x70);
}

__device__ __forceinline__ uint32_t pack_bf2(float a, float b) {
    return (uint32_t)__bfloat16_as_ushort(__float2bfloat16(a))
         | ((uint32_t)__bfloat16_as_ushort(__float2bfloat16(b)) << 16);
}

#define LDSM_X4(r0,r1,r2,r3,addr) \
    asm volatile("ldmatrix.sync.aligned.m8n8.x4.shared.b16 {%0,%1,%2,%3}, [%4];" \
        : "=r"(r0), "=r"(r1), "=r"(r2), "=r"(r3) : "r"(addr))

#define LDSM_X2(r0,r1,addr) \
    asm volatile("ldmatrix.sync.aligned.m8n8.x2.shared.b16 {%0,%1}, [%2];" \
        : "=r"(r0), "=r"(r1) : "r"(addr))

#define LDSM_X2T(r0,r1,addr) \
    asm volatile("ldmatrix.sync.aligned.m8n8.x2.trans.shared.b16 {%0,%1}, [%2];" \
        : "=r"(r0), "=r"(r1) : "r"(addr))

#define MMA16816(acc, af, bf) \
    asm volatile("mma.sync.aligned.m16n8k16.row.col.f32.bf16.bf16.f32 " \
        "{%0,%1,%2,%3}, {%4,%5,%6,%7}, {%8,%9}, {%0,%1,%2,%3};" \
        : "+f"((acc)[0]), "+f"((acc)[1]), "+f"((acc)[2]), "+f"((acc)[3]) \
        : "r"((af)[0]), "r"((af)[1]), "r"((af)[2]), "r"((af)[3]), \
          "r"((bf)[0]), "r"((bf)[1]))

// ---------------------------------------------------------------------------
// Prep: split query into bf16 hi/lo
// ---------------------------------------------------------------------------
__global__ void split_x(const float* __restrict__ X)
{
    int i = (blockIdx.x * 256 + threadIdx.x) * 4;
    float4 v = *(const float4*)(X + i);
    float h0 = __bfloat162float(__float2bfloat16(v.x));
    float h1 = __bfloat162float(__float2bfloat16(v.y));
    float h2 = __bfloat162float(__float2bfloat16(v.z));
    float h3 = __bfloat162float(__float2bfloat16(v.w));
    uint2 ph = make_uint2(pack_bf2(v.x, v.y), pack_bf2(v.z, v.w));
    uint2 pl = make_uint2(pack_bf2(v.x - h0, v.y - h1), pack_bf2(v.z - h2, v.w - h3));
    *(uint2*)(g_inh + i) = ph;
    *(uint2*)(g_inl + i) = pl;
}

// ---------------------------------------------------------------------------
// Prep: transpose + split one W [k][n] -> Wt hi/lo [n][k]
// One block per 64x64 tile.
// ---------------------------------------------------------------------------
__global__ void split_wt(const float* __restrict__ W, int widx)
{
    __shared__ float ts[64][65];
    int tid = threadIdx.x;
    int r0 = blockIdx.x * 64;   // k range
    int c0 = blockIdx.y * 64;   // n range

    #pragma unroll
    for (int i = 0; i < 4; i++) {
        int u = tid + i * 256;
        int row = u >> 4, c4 = (u & 15) * 4;
        float4 v = *(const float4*)(W + (size_t)(r0 + row) * D_ + c0 + c4);
        ts[row][c4+0] = v.x; ts[row][c4+1] = v.y;
        ts[row][c4+2] = v.z; ts[row][c4+3] = v.w;
    }
    __syncthreads();

    __nv_bfloat16* dh = g_wth[widx];
    __nv_bfloat16* dl = g_wtl[widx];
    #pragma unroll
    for (int i = 0; i < 4; i++) {
        int u = tid + i * 256;
        int nrow = u >> 4, k4 = (u & 15) * 4;
        float v0 = ts[k4+0][nrow], v1 = ts[k4+1][nrow];
        float v2 = ts[k4+2][nrow], v3 = ts[k4+3][nrow];
        float h0 = __bfloat162float(__float2bfloat16(v0));
        float h1 = __bfloat162float(__float2bfloat16(v1));
        float h2 = __bfloat162float(__float2bfloat16(v2));
        float h3 = __bfloat162float(__float2bfloat16(v3));
        size_t off = (size_t)(c0 + nrow) * D_ + r0 + k4;
        *(uint2*)(dh + off) = make_uint2(pack_bf2(v0, v1), pack_bf2(v2, v3));
        *(uint2*)(dl + off) = make_uint2(pack_bf2(v0-h0, v1-h1), pack_bf2(v2-h2, v3-h3));
    }
}

// ---------------------------------------------------------------------------
// proj_mma: C[4096,1024] = X @ W + bias via bf16x3 split mma.
// X given as hi/lo [m][k]; W as transposed hi/lo [n][k].
// mode 0/1/2: head-split bf16 hi/lo -> gq/gk/gv ; mode 3: fp32 Yout.
// 128x128 tile, 8 warps (2m x 4n), k-chunk 64.
// ---------------------------------------------------------------------------
#define PJ_SMEM (4 * 16384 + 1024)

__global__ void __launch_bounds__(256)
proj_mma(const __nv_bfloat16* __restrict__ Xh, const __nv_bfloat16* __restrict__ Xl,
         const __nv_bfloat16* __restrict__ Wth, const __nv_bfloat16* __restrict__ Wtl,
         const float* __restrict__ bias, float* __restrict__ Yout, int mode)
{
    extern __shared__ char smem_raw[];
    uint32_t raw = smem_u32(smem_raw);
    uint32_t base = (raw + 1023u) & ~1023u;
    char* smem = smem_raw + (base - raw);

    char* tXh = smem;                 uint32_t aXh = base;
    char* tXl = smem + 16384;         uint32_t aXl = base + 16384;
    char* tWh = smem + 32768;         uint32_t aWh = base + 32768;
    char* tWl = smem + 49152;         uint32_t aWl = base + 49152;

    int tid = threadIdx.x;
    int wid = tid >> 5, lane = tid & 31;
    int n0 = blockIdx.x * 128;
    int m0 = blockIdx.y * 128;
    int wm = wid >> 2, wn = wid & 3;

    float acc[4][4][4] = {};

    int a_row_l = lane & 15;
    int a_cb_l  = (lane >> 4) << 4;

    for (int k0 = 0; k0 < D_; k0 += 64) {
        __syncthreads();
        #pragma unroll
        for (int i = 0; i < 4; i++) {
            int u = tid + i * 256;
            int row = u >> 3, unit = u & 7;
            uint32_t dst = sw128((uint32_t)(row * 128 + unit * 16));
            size_t xoff = (size_t)(m0 + row) * D_ + k0 + unit * 8;
            size_t woff = (size_t)(n0 + row) * D_ + k0 + unit * 8;
            *(uint4*)(tXh + dst) = *(const uint4*)(Xh + xoff);
            *(uint4*)(tXl + dst) = *(const uint4*)(Xl + xoff);
            *(uint4*)(tWh + dst) = *(const uint4*)(Wth + woff);
            *(uint4*)(tWl + dst) = *(const uint4*)(Wtl + woff);
        }
        __syncthreads();

        #pragma unroll
        for (int ks = 0; ks < 4; ks++) {
            uint32_t a[4][4], bh[4][2], bl[4][2];
            #pragma unroll
            for (int mf = 0; mf < 4; mf++) {
                int row = wm * 64 + mf * 16 + a_row_l;
                uint32_t addr = aXh + sw128((uint32_t)(row * 128 + ks * 32 + a_cb_l));
                LDSM_X4(a[mf][0], a[mf][1], a[mf][2], a[mf][3], addr);
            }
            #pragma unroll
            for (int nf = 0; nf < 4; nf++) {
                int row = wn * 32 + nf * 8 + (lane & 7);
                uint32_t boff = sw128((uint32_t)(row * 128 + ks * 32 + (((lane >> 3) & 1) << 4)));
                LDSM_X2(bh[nf][0], bh[nf][1], aWh + boff);
                LDSM_X2(bl[nf][0], bl[nf][1], aWl + boff);
            }
            #pragma unroll
            for (int mf = 0; mf < 4; mf++)
                #pragma unroll
                for (int nf = 0; nf < 4; nf++) {
                    MMA16816(acc[mf][nf], a[mf], bh[nf]);
                    MMA16816(acc[mf][nf], a[mf], bl[nf]);
                }
            // lo(A) * hi(B)
            #pragma unroll
            for (int mf = 0; mf < 4; mf++) {
                int row = wm * 64 + mf * 16 + a_row_l;
                uint32_t addr = aXl + sw128((uint32_t)(row * 128 + ks * 32 + a_cb_l));
                LDSM_X4(a[mf][0], a[mf][1], a[mf][2], a[mf][3], addr);
            }
            #pragma unroll
            for (int mf = 0; mf < 4; mf++)
                #pragma unroll
                for (int nf = 0; nf < 4; nf++)
                    MMA16816(acc[mf][nf], a[mf], bh[nf]);
        }
    }

    // Epilogue
    int r0 = lane >> 2;
    int c0 = (lane & 3) * 2;
    __nv_bfloat16* dsth = (mode == 0) ? g_qh : (mode == 1) ? g_kh : g_vh;
    __nv_bfloat16* dstl = (mode == 0) ? g_ql : (mode == 1) ? g_kl : g_vl;

    #pragma unroll
    for (int mf = 0; mf < 4; mf++) {
        #pragma unroll
        for (int e2 = 0; e2 < 2; e2++) {
            int r = m0 + wm * 64 + mf * 16 + r0 + e2 * 8;
            #pragma unroll
            for (int nf = 0; nf < 4; nf++) {
                int c = n0 + wn * 32 + nf * 8 + c0;
                float v0 = acc[mf][nf][e2*2+0] + bias[c];
                float v1 = acc[mf][nf][e2*2+1] + bias[c+1];
                if (mode < 3) {
                    int b = r >> 11, l = r & 2047;
                    int h = c >> 6, hd = c & 63;
                    size_t idx = (((size_t)(b * H_ + h)) * L_ + l) * HD_ + hd;
                    float h0 = __bfloat162float(__float2bfloat16(v0));
                    float h1 = __bfloat162float(__float2bfloat16(v1));
                    *(uint32_t*)(dsth + idx) = pack_bf2(v0, v1);
                    *(uint32_t*)(dstl + idx) = pack_bf2(v0 - h0, v1 - h1);
                } else {
                    float2 o; o.x = v0; o.y = v1;
                    *(float2*)(Yout + (size_t)r * D_ + c) = o;
                }
            }
        }
    }
}

// ---------------------------------------------------------------------------
// Logits via mma.sync bf16x3 split (unchanged from R4 passing version)
// ---------------------------------------------------------------------------
#define LG_TILE   16384
#define LG_SMEM   (4 * LG_TILE + 1024)

__global__ void __launch_bounds__(256)
logits_mma(const float* __restrict__ abias, float* __restrict__ attn)
{
    extern __shared__ char smem_raw[];
    uint32_t raw = smem_u32(smem_raw);
    uint32_t base = (raw + 1023u) & ~1023u;
    char* smem = smem_raw + (base - raw);

    int tid  = threadIdx.x;
    int wid  = tid >> 5;
    int lane = tid & 31;
    int bh = blockIdx.z;
    int q0 = blockIdx.y * 128;
    int k0 = blockIdx.x * 128;

    const char* srcs[4] = {
        (const char*)(g_qh + ((size_t)bh * L_ + q0) * HD_),
        (const char*)(g_ql + ((size_t)bh * L_ + q0) * HD_),
        (const char*)(g_kh + ((size_t)bh * L_ + k0) * HD_),
        (const char*)(g_kl + ((size_t)bh * L_ + k0) * HD_)
    };
    #pragma unroll
    for (int t = 0; t < 4; t++) {
        char* dst = smem + t * LG_TILE;
        const char* s = srcs[t];
        #pragma unroll
        for (int u = 0; u < 4; u++) {
            uint32_t off = (uint32_t)(tid + u * 256) * 16u;
            *(uint4*)(dst + sw128(off)) = *(const uint4*)(s + off);
        }
    }
    __syncthreads();

    int wm = wid >> 2;
    int wn = wid & 3;

    float acc[4][4][4] = {};

    int a_row_l = lane & 15;
    int a_cb_l  = (lane >> 4) << 4;
    int b_row_l = lane & 7;
    int b_cb_l  = ((lane >> 3) & 1) << 4;

    #pragma unroll
    for (int pass = 0; pass < 3; pass++) {
        uint32_t aBase = base + ((pass == 2) ? LG_TILE : 0);
        uint32_t bBase = base + ((pass == 1) ? 3 * LG_TILE : 2 * LG_TILE);

        #pragma unroll
        for (int ks = 0; ks < 4; ks++) {
            uint32_t a[4][4];
            #pragma unroll
            for (int mf = 0; mf < 4; mf++) {
                int row = wm * 64 + mf * 16 + a_row_l;
                uint32_t addr = aBase + sw128((uint32_t)(row * 128 + ks * 32 + a_cb_l));
                LDSM_X4(a[mf][0], a[mf][1], a[mf][2], a[mf][3], addr);
            }
            uint32_t b[4][2];
            #pragma unroll
            for (int nf = 0; nf < 4; nf++) {
                int row = wn * 32 + nf * 8 + b_row_l;
                uint32_t addr = bBase + sw128((uint32_t)(row * 128 + ks * 32 + b_cb_l));
                LDSM_X2(b[nf][0], b[nf][1], addr);
            }
            #pragma unroll
            for (int mf = 0; mf < 4; mf++)
                #pragma unroll
                for (int nf = 0; nf < 4; nf++)
                    MMA16816(acc[mf][nf], a[mf], b[nf]);
        }
    }

    int b = bh >> 4;
    size_t attn_base = (size_t)bh * L_ * L_;
    int qbase = q0 + wm * 64;
    int kbase = k0 + wn * 32;
    int r0 = lane >> 2;
    int c0 = (lane & 3) * 2;

    #pragma unroll
    for (int mf = 0; mf < 4; mf++) {
        #pragma unroll
        for (int e2 = 0; e2 < 2; e2++) {
            int q = qbase + mf * 16 + r0 + e2 * 8;
            const float* brow = abias + ((size_t)b * L_ + q) * L_;
            float* orow = attn + attn_base + (size_t)q * L_;
            #pragma unroll
            for (int nf = 0; nf < 4; nf++) {
                int k = kbase + nf * 8 + c0;
                float2 bb = *(const float2*)(brow + k);
                float2 o;
                o.x = acc[mf][nf][e2 * 2 + 0] * 0.125f + bb.x;
                o.y = acc[mf][nf][e2 * 2 + 1] * 0.125f + bb.y;
                *(float2*)(orow + k) = o;
            }
        }
    }
}

// ---------------------------------------------------------------------------
// Row softmax over last dim (L_=2048), in place. One block per row.
// ---------------------------------------------------------------------------
__global__ void softmax_kernel(float* __restrict__ attn)
{
    size_t row = blockIdx.x;
    float* p = attn + row * L_;
    int tid = threadIdx.x;
    int ln = tid & 31, wid = tid >> 5;

    float v[8];
    #pragma unroll
    for (int i = 0; i < 2; i++) {
        float4 t = *(const float4*)(p + tid * 8 + i * 4);
        v[i*4+0] = t.x; v[i*4+1] = t.y; v[i*4+2] = t.z; v[i*4+3] = t.w;
    }

    __shared__ float sm[16];

    float m = v[0];
    #pragma unroll
    for (int i = 1; i < 8; i++) m = fmaxf(m, v[i]);
    #pragma unroll
    for (int o = 16; o > 0; o >>= 1) m = fmaxf(m, __shfl_xor_sync(~0u, m, o));
    if (ln == 0) sm[wid] = m;
    __syncthreads();
    m = sm[0];
    #pragma unroll
    for (int k = 1; k < 8; k++) m = fmaxf(m, sm[k]);

    float s = 0.f;
    #pragma unroll
    for (int i = 0; i < 8; i++) { v[i] = __expf(v[i] - m); s += v[i]; }
    #pragma unroll
    for (int o = 16; o > 0; o >>= 1) s += __shfl_xor_sync(~0u, s, o);
    if (ln == 0) sm[8 + wid] = s;
    __syncthreads();
    s = 0.f;
    #pragma unroll
    for (int k = 0; k < 8; k++) s += sm[8 + k];

    float inv = 1.0f / s;
    #pragma unroll
    for (int i = 0; i < 2; i++) {
        float4 t;
        t.x = v[i*4+0] * inv; t.y = v[i*4+1] * inv;
        t.z = v[i*4+2] * inv; t.w = v[i*4+3] * inv;
        *(float4*)(p + tid * 8 + i * 4) = t;
    }
}

// ---------------------------------------------------------------------------
// av_mma: x = attn @ V per (b,h). attn fp32 (post-softmax) converted to bf16
// hi/lo on the fly; V from g_vh/g_vl ([B,H,L,HD], 128B rows), B operand via
// ldmatrix.x2.trans. C tile 128(q) x 64(hd); 8 warps (4m x 2n); k-chunk 64.
// Output: g_xh/g_xl bf16 split [B,L,D].
// ---------------------------------------------------------------------------
#define AV_SMEM (16384 * 2 + 8192 * 2 + 1024)

__global__ void __launch_bounds__(256)
av_mma(const float* __restrict__ attn)
{
    extern __shared__ char smem_raw[];
    uint32_t raw = smem_u32(smem_raw);
    uint32_t base = (raw + 1023u) & ~1023u;
    char* smem = smem_raw + (base - raw);

    char* tAh = smem;                 uint32_t aAh = base;
    char* tAl = smem + 16384;         uint32_t aAl = base + 16384;
    char* tVh = smem + 32768;         uint32_t aVh = base + 32768;
    char* tVl = smem + 40960;         uint32_t aVl = base + 40960;

    int tid = threadIdx.x;
    int wid = tid >> 5, lane = tid & 31;
    int bh = blockIdx.y;
    int q0 = blockIdx.x * 128;
    int wm = wid >> 1;      // 0..3 : 32 q-rows each
    int wn = wid & 1;       // 0..1 : 32 hd each

    const float* A = attn + (size_t)bh * L_ * L_;
    const __nv_bfloat16* Vh = g_vh + (size_t)bh * L_ * HD_;
    const __nv_bfloat16* Vl = g_vl + (size_t)bh * L_ * HD_;

    float acc[2][4][4] = {};

    int a_row_l = lane & 15;
    int a_cb_l  = (lane >> 4) << 4;

    for (int k0 = 0; k0 < L_; k0 += 64) {
        __syncthreads();
        // attn tile: 128 rows x 64 fp32 -> split to bf16 hi/lo
        #pragma unroll
        for (int i = 0; i < 8; i++) {
            int u = tid + i * 256;
            int row = u >> 4, f4 = (u & 15) * 4;
            float4 t = *(const float4*)(A + (size_t)(q0 + row) * L_ + k0 + f4);
            float h0 = __bfloat162float(__float2bfloat16(t.x));
            float h1 = __bfloat162float(__float2bfloat16(t.y));
            float h2 = __bfloat162float(__float2bfloat16(t.z));
            float h3 = __bfloat162float(__float2bfloat16(t.w));
            uint32_t so = sw128((uint32_t)(row * 128 + f4 * 2));
            *(uint2*)(tAh + so) = make_uint2(pack_bf2(t.x, t.y), pack_bf2(t.z, t.w));
            *(uint2*)(tAl + so) = make_uint2(pack_bf2(t.x - h0, t.y - h1),
                                             pack_bf2(t.z - h2, t.w - h3));
        }
        // V tiles: 64 rows (k) x 64 hd, 128B rows
        #pragma unroll
        for (int i = 0; i < 2; i++) {
            int u = tid + i * 256;
            int row = u >> 3, unit = u & 7;
            uint32_t dst = sw128((uint32_t)(row * 128 + unit * 16));
            size_t off = (size_t)(k0 + row) * HD_ + unit * 8;
            *(uint4*)(tVh + dst) = *(const uint4*)(Vh + off);
            *(uint4*)(tVl + dst) = *(const uint4*)(Vl + off);
        }
        __syncthreads();

        #pragma unroll
        for (int ks = 0; ks < 4; ks++) {
            uint32_t a[2][4], bh2[4][2], bl2[4][2];
            #pragma unroll
            for (int mf = 0; mf < 2; mf++) {
                int row = wm * 32 + mf * 16 + a_row_l;
                uint32_t addr = aAh + sw128((uint32_t)(row * 128 + ks * 32 + a_cb_l));
                LDSM_X4(a[mf][0], a[mf][1], a[mf][2], a[mf][3], addr);
            }
            #pragma unroll
            for (int nf = 0; nf < 4; nf++) {
                int row = ks * 16 + (lane & 15);
                uint32_t boff = sw128((uint32_t)(row * 128 + wn * 64 + nf * 16));
                LDSM_X2T(bh2[nf][0], bh2[nf][1], aVh + boff);
                LDSM_X2T(bl2[nf][0], bl2[nf][1], aVl + boff);
            }
            #pragma unroll
            for (int mf = 0; mf < 2; mf++)
                #pragma unroll
                for (int nf = 0; nf < 4; nf++) {
                    MMA16816(acc[mf][nf], a[mf], bh2[nf]);
                    MMA16816(acc[mf][nf], a[mf], bl2[nf]);
                }
            #pragma unroll
            for (int mf = 0; mf < 2; mf++) {
                int row = wm * 32 + mf * 16 + a_row_l;
                uint32_t addr = aAl + sw128((uint32_t)(row * 128 + ks * 32 + a_cb_l));
                LDSM_X4(a[mf][0], a[mf][1], a[mf][2], a[mf][3], addr);
            }
            #pragma unroll
            for (int mf = 0; mf < 2; mf++)
                #pragma unroll
                for (int nf = 0; nf < 4; nf++)
                    MMA16816(acc[mf][nf], a[mf], bh2[nf]);
        }
    }

    // Epilogue: write bf16 hi/lo x into [B,L,D]
    int b = bh >> 4, h = bh & 15;
    int r0 = lane >> 2;
    int c0 = (lane & 3) * 2;

    #pragma unroll
    for (int mf = 0; mf < 2; mf++) {
        #pragma unroll
        for (int e2 = 0; e2 < 2; e2++) {
            int q = q0 + wm * 32 + mf * 16 + r0 + e2 * 8;
            #pragma unroll
            for (int nf = 0; nf < 4; nf++) {
                int hd = wn * 32 + nf * 8 + c0;
                float v0 = acc[mf][nf][e2*2+0];
                float v1 = acc[mf][nf][e2*2+1];
                float h0 = __bfloat162float(__float2bfloat16(v0));
                float h1 = __bfloat162float(__float2bfloat16(v1));
                size_t idx = ((size_t)(b * L_ + q)) * D_ + h * HD_ + hd;
                *(uint32_t*)(g_xh + idx) = pack_bf2(v0, v1);
                *(uint32_t*)(g_xl + idx) = pack_bf2(v0 - h0, v1 - h1);
            }
        }
    }
}

// ---------------------------------------------------------------------------
extern "C" void kernel_launch(void* const* d_in, const int* in_sizes, int n_in,
                              void* d_out, int out_size)
{
    const float* query = (const float*)d_in[0];
    const float* abias = (const float*)d_in[1];
    const float* Wq    = (const float*)d_in[2];
    const float* bq    = (const float*)d_in[3];
    const float* Wk    = (const float*)d_in[4];
    const float* bk    = (const float*)d_in[5];
    const float* Wv    = (const float*)d_in[6];
    const float* bv    = (const float*)d_in[7];
    const float* Wo    = (const float*)d_in[8];
    const float* bo    = (const float*)d_in[9];

    float* out  = (float*)d_out;
    float* ans  = out;                              // [B,L,D]
    float* attn = out + (size_t)M_ * D_;            // [B,H,L,L]

    cudaFuncSetAttribute(logits_mma, cudaFuncAttributeMaxDynamicSharedMemorySize, LG_SMEM);
    cudaFuncSetAttribute(proj_mma,   cudaFuncAttributeMaxDynamicSharedMemorySize, PJ_SMEM);
    cudaFuncSetAttribute(av_mma,     cudaFuncAttributeMaxDynamicSharedMemorySize, AV_SMEM);

    // device-symbol addresses (host side)
    __nv_bfloat16 *p_inh, *p_inl, *p_wth, *p_wtl, *p_xh, *p_xl;
    cudaGetSymbolAddress((void**)&p_inh, g_inh);
    cudaGetSymbolAddress((void**)&p_inl, g_inl);
    cudaGetSymbolAddress((void**)&p_wth, g_wth);
    cudaGetSymbolAddress((void**)&p_wtl, g_wtl);
    cudaGetSymbolAddress((void**)&p_xh, g_xh);
    cudaGetSymbolAddress((void**)&p_xl, g_xl);

    // Prep splits
    split_x<<<M_ * D_ / 1024, 256>>>(query);
    dim3 gwt(D_ / 64, D_ / 64);
    split_wt<<<gwt, 256>>>(Wq, 0);
    split_wt<<<gwt, 256>>>(Wk, 1);
    split_wt<<<gwt, 256>>>(Wv, 2);
    split_wt<<<gwt, 256>>>(Wo, 3);

    // Projections (tensor core)
    dim3 gproj(D_ / 128, M_ / 128);
    proj_mma<<<gproj, 256, PJ_SMEM>>>(p_inh, p_inl, p_wth + 0 * (size_t)D_ * D_,
                                      p_wtl + 0 * (size_t)D_ * D_, bq, nullptr, 0);
    proj_mma<<<gproj, 256, PJ_SMEM>>>(p_inh, p_inl, p_wth + 1 * (size_t)D_ * D_,
                                      p_wtl + 1 * (size_t)D_ * D_, bk, nullptr, 1);
    proj_mma<<<gproj, 256, PJ_SMEM>>>(p_inh, p_inl, p_wth + 2 * (size_t)D_ * D_,
                                      p_wtl + 2 * (size_t)D_ * D_, bv, nullptr, 2);

    logits_mma<<<dim3(L_ / 128, L_ / 128, B_ * H_), 256, LG_SMEM>>>(abias, attn);

    softmax_kernel<<<B_ * H_ * L_, 256>>>(attn);

    av_mma<<<dim3(L_ / 128, B_ * H_), 256, AV_SMEM>>>(attn);

    proj_mma<<<gproj, 256, PJ_SMEM>>>(p_xh, p_xl, p_wth + 3 * (size_t)D_ * D_,
                                      p_wtl + 3 * (size_t)D_ * D_, bo, ans, 3);
}

// round 6
// speedup vs baseline: 1.9297x; 1.0093x over previous
#include <cuda_runtime.h>
#include <cuda_bf16.h>
#include <cstdint>

#define B_  2
#define L_  2048
#define D_  1024
#define H_  16
#define HD_ 64
#define M_  (B_ * L_)   // 4096 rows for the projection GEMMs
#define NBH (B_ * H_)   // 32
#define KT_ (L_ / 128)  // 16 k-tiles per row in logits

// ---------------------------------------------------------------------------
// Scratch (device globals)
// ---------------------------------------------------------------------------
__device__ __nv_bfloat16 g_inh[M_ * D_], g_inl[M_ * D_];      // split query
__device__ __nv_bfloat16 g_wth[4][D_ * D_], g_wtl[4][D_ * D_]; // split W^T [n][k]
__device__ __nv_bfloat16 g_qh[B_ * H_ * L_ * HD_], g_ql[B_ * H_ * L_ * HD_];
__device__ __nv_bfloat16 g_kh[B_ * H_ * L_ * HD_], g_kl[B_ * H_ * L_ * HD_];
__device__ __nv_bfloat16 g_vh[B_ * H_ * L_ * HD_], g_vl[B_ * H_ * L_ * HD_];
__device__ __nv_bfloat16 g_xh[M_ * D_], g_xl[M_ * D_];        // split attn@V out
__device__ float g_pmax[NBH * L_ * KT_];   // per-tile row max
__device__ float g_psum[NBH * L_ * KT_];   // per-tile row sum of exp(v - tilemax)
__device__ float g_rm[NBH * L_];           // final row max
__device__ float g_ri[NBH * L_];           // final 1/rowsum

__device__ __forceinline__ uint32_t smem_u32(const void* p) {
    uint32_t a;
    asm("{ .reg .u64 t; cvta.to.shared.u64 t, %1; cvt.u32.u64 %0, t; }"
        : "=r"(a) : "l"(p));
    return a;
}

__device__ __forceinline__ uint32_t sw128(uint32_t off) {
    return off ^ ((off >> 3) & 0x70);
}

__device__ __forceinline__ uint32_t pack_bf2(float a, float b) {
    return (uint32_t)__bfloat16_as_ushort(__float2bfloat16(a))
         | ((uint32_t)__bfloat16_as_ushort(__float2bfloat16(b)) << 16);
}

#define LDSM_X4(r0,r1,r2,r3,addr) \
    asm volatile("ldmatrix.sync.aligned.m8n8.x4.shared.b16 {%0,%1,%2,%3}, [%4];" \
        : "=r"(r0), "=r"(r1), "=r"(r2), "=r"(r3) : "r"(addr))

#define LDSM_X2(r0,r1,addr) \
    asm volatile("ldmatrix.sync.aligned.m8n8.x2.shared.b16 {%0,%1}, [%2];" \
        : "=r"(r0), "=r"(r1) : "r"(addr))

#define LDSM_X2T(r0,r1,addr) \
    asm volatile("ldmatrix.sync.aligned.m8n8.x2.trans.shared.b16 {%0,%1}, [%2];" \
        : "=r"(r0), "=r"(r1) : "r"(addr))

#define MMA16816(acc, af, bf) \
    asm volatile("mma.sync.aligned.m16n8k16.row.col.f32.bf16.bf16.f32 " \
        "{%0,%1,%2,%3}, {%4,%5,%6,%7}, {%8,%9}, {%0,%1,%2,%3};" \
        : "+f"((acc)[0]), "+f"((acc)[1]), "+f"((acc)[2]), "+f"((acc)[3]) \
        : "r"((af)[0]), "r"((af)[1]), "r"((af)[2]), "r"((af)[3]), \
          "r"((bf)[0]), "r"((bf)[1]))

// ---------------------------------------------------------------------------
// Prep: split query into bf16 hi/lo
// ---------------------------------------------------------------------------
__global__ void split_x(const float* __restrict__ X)
{
    int i = (blockIdx.x * 256 + threadIdx.x) * 4;
    float4 v = *(const float4*)(X + i);
    float h0 = __bfloat162float(__float2bfloat16(v.x));
    float h1 = __bfloat162float(__float2bfloat16(v.y));
    float h2 = __bfloat162float(__float2bfloat16(v.z));
    float h3 = __bfloat162float(__float2bfloat16(v.w));
    *(uint2*)(g_inh + i) = make_uint2(pack_bf2(v.x, v.y), pack_bf2(v.z, v.w));
    *(uint2*)(g_inl + i) = make_uint2(pack_bf2(v.x - h0, v.y - h1), pack_bf2(v.z - h2, v.w - h3));
}

// ---------------------------------------------------------------------------
// Prep: transpose + split one W [k][n] -> Wt hi/lo [n][k]
// ---------------------------------------------------------------------------
__global__ void split_wt(const float* __restrict__ W, int widx)
{
    __shared__ float ts[64][65];
    int tid = threadIdx.x;
    int r0 = blockIdx.x * 64;   // k range
    int c0 = blockIdx.y * 64;   // n range

    #pragma unroll
    for (int i = 0; i < 4; i++) {
        int u = tid + i * 256;
        int row = u >> 4, c4 = (u & 15) * 4;
        float4 v = *(const float4*)(W + (size_t)(r0 + row) * D_ + c0 + c4);
        ts[row][c4+0] = v.x; ts[row][c4+1] = v.y;
        ts[row][c4+2] = v.z; ts[row][c4+3] = v.w;
    }
    __syncthreads();

    __nv_bfloat16* dh = g_wth[widx];
    __nv_bfloat16* dl = g_wtl[widx];
    #pragma unroll
    for (int i = 0; i < 4; i++) {
        int u = tid + i * 256;
        int nrow = u >> 4, k4 = (u & 15) * 4;
        float v0 = ts[k4+0][nrow], v1 = ts[k4+1][nrow];
        float v2 = ts[k4+2][nrow], v3 = ts[k4+3][nrow];
        float h0 = __bfloat162float(__float2bfloat16(v0));
        float h1 = __bfloat162float(__float2bfloat16(v1));
        float h2 = __bfloat162float(__float2bfloat16(v2));
        float h3 = __bfloat162float(__float2bfloat16(v3));
        size_t off = (size_t)(c0 + nrow) * D_ + r0 + k4;
        *(uint2*)(dh + off) = make_uint2(pack_bf2(v0, v1), pack_bf2(v2, v3));
        *(uint2*)(dl + off) = make_uint2(pack_bf2(v0-h0, v1-h1), pack_bf2(v2-h2, v3-h3));
    }
}

// ---------------------------------------------------------------------------
// proj_mma (unchanged from R5)
// ---------------------------------------------------------------------------
#define PJ_SMEM (4 * 16384 + 1024)

__global__ void __launch_bounds__(256)
proj_mma(const __nv_bfloat16* __restrict__ Xh, const __nv_bfloat16* __restrict__ Xl,
         const __nv_bfloat16* __restrict__ Wth, const __nv_bfloat16* __restrict__ Wtl,
         const float* __restrict__ bias, float* __restrict__ Yout, int mode)
{
    extern __shared__ char smem_raw[];
    uint32_t raw = smem_u32(smem_raw);
    uint32_t base = (raw + 1023u) & ~1023u;
    char* smem = smem_raw + (base - raw);

    char* tXh = smem;                 uint32_t aXh = base;
    char* tXl = smem + 16384;         uint32_t aXl = base + 16384;
    char* tWh = smem + 32768;         uint32_t aWh = base + 32768;
    char* tWl = smem + 49152;         uint32_t aWl = base + 49152;

    int tid = threadIdx.x;
    int wid = tid >> 5, lane = tid & 31;
    int n0 = blockIdx.x * 128;
    int m0 = blockIdx.y * 128;
    int wm = wid >> 2, wn = wid & 3;

    float acc[4][4][4] = {};

    int a_row_l = lane & 15;
    int a_cb_l  = (lane >> 4) << 4;

    for (int k0 = 0; k0 < D_; k0 += 64) {
        __syncthreads();
        #pragma unroll
        for (int i = 0; i < 4; i++) {
            int u = tid + i * 256;
            int row = u >> 3, unit = u & 7;
            uint32_t dst = sw128((uint32_t)(row * 128 + unit * 16));
            size_t xoff = (size_t)(m0 + row) * D_ + k0 + unit * 8;
            size_t woff = (size_t)(n0 + row) * D_ + k0 + unit * 8;
            *(uint4*)(tXh + dst) = *(const uint4*)(Xh + xoff);
            *(uint4*)(tXl + dst) = *(const uint4*)(Xl + xoff);
            *(uint4*)(tWh + dst) = *(const uint4*)(Wth + woff);
            *(uint4*)(tWl + dst) = *(const uint4*)(Wtl + woff);
        }
        __syncthreads();

        #pragma unroll
        for (int ks = 0; ks < 4; ks++) {
            uint32_t a[4][4], bh[4][2], bl[4][2];
            #pragma unroll
            for (int mf = 0; mf < 4; mf++) {
                int row = wm * 64 + mf * 16 + a_row_l;
                uint32_t addr = aXh + sw128((uint32_t)(row * 128 + ks * 32 + a_cb_l));
                LDSM_X4(a[mf][0], a[mf][1], a[mf][2], a[mf][3], addr);
            }
            #pragma unroll
            for (int nf = 0; nf < 4; nf++) {
                int row = wn * 32 + nf * 8 + (lane & 7);
                uint32_t boff = sw128((uint32_t)(row * 128 + ks * 32 + (((lane >> 3) & 1) << 4)));
                LDSM_X2(bh[nf][0], bh[nf][1], aWh + boff);
                LDSM_X2(bl[nf][0], bl[nf][1], aWl + boff);
            }
            #pragma unroll
            for (int mf = 0; mf < 4; mf++)
                #pragma unroll
                for (int nf = 0; nf < 4; nf++) {
                    MMA16816(acc[mf][nf], a[mf], bh[nf]);
                    MMA16816(acc[mf][nf], a[mf], bl[nf]);
                }
            #pragma unroll
            for (int mf = 0; mf < 4; mf++) {
                int row = wm * 64 + mf * 16 + a_row_l;
                uint32_t addr = aXl + sw128((uint32_t)(row * 128 + ks * 32 + a_cb_l));
                LDSM_X4(a[mf][0], a[mf][1], a[mf][2], a[mf][3], addr);
            }
            #pragma unroll
            for (int mf = 0; mf < 4; mf++)
                #pragma unroll
                for (int nf = 0; nf < 4; nf++)
                    MMA16816(acc[mf][nf], a[mf], bh[nf]);
        }
    }

    int r0 = lane >> 2;
    int c0 = (lane & 3) * 2;
    __nv_bfloat16* dsth = (mode == 0) ? g_qh : (mode == 1) ? g_kh : g_vh;
    __nv_bfloat16* dstl = (mode == 0) ? g_ql : (mode == 1) ? g_kl : g_vl;

    #pragma unroll
    for (int mf = 0; mf < 4; mf++) {
        #pragma unroll
        for (int e2 = 0; e2 < 2; e2++) {
            int r = m0 + wm * 64 + mf * 16 + r0 + e2 * 8;
            #pragma unroll
            for (int nf = 0; nf < 4; nf++) {
                int c = n0 + wn * 32 + nf * 8 + c0;
                float v0 = acc[mf][nf][e2*2+0] + bias[c];
                float v1 = acc[mf][nf][e2*2+1] + bias[c+1];
                if (mode < 3) {
                    int b = r >> 11, l = r & 2047;
                    int h = c >> 6, hd = c & 63;
                    size_t idx = (((size_t)(b * H_ + h)) * L_ + l) * HD_ + hd;
                    float h0 = __bfloat162float(__float2bfloat16(v0));
                    float h1 = __bfloat162float(__float2bfloat16(v1));
                    *(uint32_t*)(dsth + idx) = pack_bf2(v0, v1);
                    *(uint32_t*)(dstl + idx) = pack_bf2(v0 - h0, v1 - h1);
                } else {
                    float2 o; o.x = v0; o.y = v1;
                    *(float2*)(Yout + (size_t)r * D_ + c) = o;
                }
            }
        }
    }
}

// ---------------------------------------------------------------------------
// Logits via mma.sync bf16x3 split + per-tile softmax stats in the epilogue.
// Writes pre-softmax attn and (tilemax, tile sum-of-exp) per row per k-tile.
// ---------------------------------------------------------------------------
#define LG_TILE   16384
#define LG_SMEM   (4 * LG_TILE + 1024)

__global__ void __launch_bounds__(256)
logits_mma(const float* __restrict__ abias, float* __restrict__ attn)
{
    extern __shared__ char smem_raw[];
    uint32_t raw = smem_u32(smem_raw);
    uint32_t base = (raw + 1023u) & ~1023u;
    char* smem = smem_raw + (base - raw);

    int tid  = threadIdx.x;
    int wid  = tid >> 5;
    int lane = tid & 31;
    int bh = blockIdx.z;
    int q0 = blockIdx.y * 128;
    int k0 = blockIdx.x * 128;

    const char* srcs[4] = {
        (const char*)(g_qh + ((size_t)bh * L_ + q0) * HD_),
        (const char*)(g_ql + ((size_t)bh * L_ + q0) * HD_),
        (const char*)(g_kh + ((size_t)bh * L_ + k0) * HD_),
        (const char*)(g_kl + ((size_t)bh * L_ + k0) * HD_)
    };
    #pragma unroll
    for (int t = 0; t < 4; t++) {
        char* dst = smem + t * LG_TILE;
        const char* s = srcs[t];
        #pragma unroll
        for (int u = 0; u < 4; u++) {
            uint32_t off = (uint32_t)(tid + u * 256) * 16u;
            *(uint4*)(dst + sw128(off)) = *(const uint4*)(s + off);
        }
    }
    __syncthreads();

    int wm = wid >> 2;
    int wn = wid & 3;

    float acc[4][4][4] = {};

    int a_row_l = lane & 15;
    int a_cb_l  = (lane >> 4) << 4;
    int b_row_l = lane & 7;
    int b_cb_l  = ((lane >> 3) & 1) << 4;

    #pragma unroll
    for (int pass = 0; pass < 3; pass++) {
        uint32_t aBase = base + ((pass == 2) ? LG_TILE : 0);
        uint32_t bBase = base + ((pass == 1) ? 3 * LG_TILE : 2 * LG_TILE);

        #pragma unroll
        for (int ks = 0; ks < 4; ks++) {
            uint32_t a[4][4];
            #pragma unroll
            for (int mf = 0; mf < 4; mf++) {
                int row = wm * 64 + mf * 16 + a_row_l;
                uint32_t addr = aBase + sw128((uint32_t)(row * 128 + ks * 32 + a_cb_l));
                LDSM_X4(a[mf][0], a[mf][1], a[mf][2], a[mf][3], addr);
            }
            uint32_t b[4][2];
            #pragma unroll
            for (int nf = 0; nf < 4; nf++) {
                int row = wn * 32 + nf * 8 + b_row_l;
                uint32_t addr = bBase + sw128((uint32_t)(row * 128 + ks * 32 + b_cb_l));
                LDSM_X2(b[nf][0], b[nf][1], addr);
            }
            #pragma unroll
            for (int mf = 0; mf < 4; mf++)
                #pragma unroll
                for (int nf = 0; nf < 4; nf++)
                    MMA16816(acc[mf][nf], a[mf], b[nf]);
        }
    }

    // --- Epilogue phase 0: finalize (scale + bias) into acc, write attn ---
    int b = bh >> 4;
    size_t attn_base = (size_t)bh * L_ * L_;
    int qbase = q0 + wm * 64;
    int kbase = k0 + wn * 32;
    int r0 = lane >> 2;
    int c0 = (lane & 3) * 2;

    #pragma unroll
    for (int mf = 0; mf < 4; mf++) {
        #pragma unroll
        for (int e2 = 0; e2 < 2; e2++) {
            int q = qbase + mf * 16 + r0 + e2 * 8;
            const float* brow = abias + ((size_t)b * L_ + q) * L_;
            float* orow = attn + attn_base + (size_t)q * L_;
            #pragma unroll
            for (int nf = 0; nf < 4; nf++) {
                int k = kbase + nf * 8 + c0;
                float2 bb = *(const float2*)(brow + k);
                float v0 = acc[mf][nf][e2*2+0] * 0.125f + bb.x;
                float v1 = acc[mf][nf][e2*2+1] * 0.125f + bb.y;
                acc[mf][nf][e2*2+0] = v0;
                acc[mf][nf][e2*2+1] = v1;
                *(float2*)(orow + k) = make_float2(v0, v1);
            }
        }
    }

    // --- Softmax partial stats (reuse tile SMEM after all warps' mma done) ---
    __syncthreads();
    float* smax = (float*)smem;          // [128][4]
    float* ssum = smax + 512;            // [128][4]

    #pragma unroll
    for (int mf = 0; mf < 4; mf++) {
        #pragma unroll
        for (int e2 = 0; e2 < 2; e2++) {
            float rm = -3.4e38f;
            #pragma unroll
            for (int nf = 0; nf < 4; nf++)
                rm = fmaxf(rm, fmaxf(acc[mf][nf][e2*2], acc[mf][nf][e2*2+1]));
            rm = fmaxf(rm, __shfl_xor_sync(~0u, rm, 1));
            rm = fmaxf(rm, __shfl_xor_sync(~0u, rm, 2));
            int rw = wm * 64 + mf * 16 + e2 * 8 + r0;
            if ((lane & 3) == 0) smax[rw * 4 + wn] = rm;
        }
    }
    __syncthreads();
    #pragma unroll
    for (int mf = 0; mf < 4; mf++) {
        #pragma unroll
        for (int e2 = 0; e2 < 2; e2++) {
            int rw = wm * 64 + mf * 16 + e2 * 8 + r0;
            float tm = fmaxf(fmaxf(smax[rw*4+0], smax[rw*4+1]),
                             fmaxf(smax[rw*4+2], smax[rw*4+3]));
            float s = 0.f;
            #pragma unroll
            for (int nf = 0; nf < 4; nf++)
                s += __expf(acc[mf][nf][e2*2] - tm) + __expf(acc[mf][nf][e2*2+1] - tm);
            s += __shfl_xor_sync(~0u, s, 1);
            s += __shfl_xor_sync(~0u, s, 2);
            if ((lane & 3) == 0) ssum[rw * 4 + wn] = s;
        }
    }
    __syncthreads();
    if (tid < 128) {
        float tm = fmaxf(fmaxf(smax[tid*4+0], smax[tid*4+1]),
                         fmaxf(smax[tid*4+2], smax[tid*4+3]));
        float s = ssum[tid*4+0] + ssum[tid*4+1] + ssum[tid*4+2] + ssum[tid*4+3];
        size_t sidx = ((size_t)bh * L_ + q0 + tid) * KT_ + blockIdx.x;
        g_pmax[sidx] = tm;
        g_psum[sidx] = s;
    }
}

// ---------------------------------------------------------------------------
// Combine per-tile stats -> row max M and 1/rowsum
// ---------------------------------------------------------------------------
__global__ void combine_stats()
{
    int row = blockIdx.x * 256 + threadIdx.x;   // < NBH*L_
    const float* pm = g_pmax + (size_t)row * KT_;
    const float* ps = g_psum + (size_t)row * KT_;
    float M = -3.4e38f;
    #pragma unroll
    for (int t = 0; t < KT_; t++) M = fmaxf(M, pm[t]);
    float S = 0.f;
    #pragma unroll
    for (int t = 0; t < KT_; t++) S += ps[t] * __expf(pm[t] - M);
    g_rm[row] = M;
    g_ri[row] = 1.0f / S;
}

// ---------------------------------------------------------------------------
// av_fused: reads pre-softmax attn, applies p = exp(v-M)/S, writes softmaxed
// attn back in place, and accumulates x = P @ V via bf16x3 split mma.
// C tile 128(q) x 64(hd); 8 warps (4m x 2n); k-chunk 64.
// ---------------------------------------------------------------------------
#define AV_SMEM (16384 * 2 + 8192 * 2 + 1024 + 1024)

__global__ void __launch_bounds__(256)
av_fused(float* __restrict__ attn)
{
    extern __shared__ char smem_raw[];
    uint32_t raw = smem_u32(smem_raw);
    uint32_t base = (raw + 1023u) & ~1023u;
    char* smem = smem_raw + (base - raw);

    char* tAh = smem;                 uint32_t aAh = base;
    char* tAl = smem + 16384;         uint32_t aAl = base + 16384;
    char* tVh = smem + 32768;         uint32_t aVh = base + 32768;
    char* tVl = smem + 40960;         uint32_t aVl = base + 40960;
    float* s_m  = (float*)(smem + 49152);   // [128]
    float* s_ri = s_m + 128;                // [128]

    int tid = threadIdx.x;
    int wid = tid >> 5, lane = tid & 31;
    int bh = blockIdx.y;
    int q0 = blockIdx.x * 128;
    int wm = wid >> 1;      // 0..3 : 32 q-rows each
    int wn = wid & 1;       // 0..1 : 32 hd each

    float* A = attn + (size_t)bh * L_ * L_;
    const __nv_bfloat16* Vh = g_vh + (size_t)bh * L_ * HD_;
    const __nv_bfloat16* Vl = g_vl + (size_t)bh * L_ * HD_;

    if (tid < 128) {
        size_t r = (size_t)bh * L_ + q0 + tid;
        s_m[tid]  = g_rm[r];
        s_ri[tid] = g_ri[r];
    }

    float acc[2][4][4] = {};

    int a_row_l = lane & 15;
    int a_cb_l  = (lane >> 4) << 4;

    for (int k0 = 0; k0 < L_; k0 += 64) {
        __syncthreads();
        // attn tile: 128 rows x 64 fp32 -> softmax-apply -> write back + split bf16
        #pragma unroll
        for (int i = 0; i < 8; i++) {
            int u = tid + i * 256;
            int row = u >> 4, f4 = (u & 15) * 4;
            float* gp = A + (size_t)(q0 + row) * L_ + k0 + f4;
            float4 t = *(const float4*)gp;
            float m = s_m[row], ri = s_ri[row];
            t.x = __expf(t.x - m) * ri;
            t.y = __expf(t.y - m) * ri;
            t.z = __expf(t.z - m) * ri;
            t.w = __expf(t.w - m) * ri;
            *(float4*)gp = t;
            float h0 = __bfloat162float(__float2bfloat16(t.x));
            float h1 = __bfloat162float(__float2bfloat16(t.y));
            float h2 = __bfloat162float(__float2bfloat16(t.z));
            float h3 = __bfloat162float(__float2bfloat16(t.w));
            uint32_t so = sw128((uint32_t)(row * 128 + f4 * 2));
            *(uint2*)(tAh + so) = make_uint2(pack_bf2(t.x, t.y), pack_bf2(t.z, t.w));
            *(uint2*)(tAl + so) = make_uint2(pack_bf2(t.x - h0, t.y - h1),
                                             pack_bf2(t.z - h2, t.w - h3));
        }
        // V tiles: 64 rows (k) x 64 hd, 128B rows
        #pragma unroll
        for (int i = 0; i < 2; i++) {
            int u = tid + i * 256;
            int row = u >> 3, unit = u & 7;
            uint32_t dst = sw128((uint32_t)(row * 128 + unit * 16));
            size_t off = (size_t)(k0 + row) * HD_ + unit * 8;
            *(uint4*)(tVh + dst) = *(const uint4*)(Vh + off);
            *(uint4*)(tVl + dst) = *(const uint4*)(Vl + off);
        }
        __syncthreads();

        #pragma unroll
        for (int ks = 0; ks < 4; ks++) {
            uint32_t a[2][4], bh2[4][2], bl2[4][2];
            #pragma unroll
            for (int mf = 0; mf < 2; mf++) {
                int row = wm * 32 + mf * 16 + a_row_l;
                uint32_t addr = aAh + sw128((uint32_t)(row * 128 + ks * 32 + a_cb_l));
                LDSM_X4(a[mf][0], a[mf][1], a[mf][2], a[mf][3], addr);
            }
            #pragma unroll
            for (int nf = 0; nf < 4; nf++) {
                int row = ks * 16 + (lane & 15);
                uint32_t boff = sw128((uint32_t)(row * 128 + wn * 64 + nf * 16));
                LDSM_X2T(bh2[nf][0], bh2[nf][1], aVh + boff);
                LDSM_X2T(bl2[nf][0], bl2[nf][1], aVl + boff);
            }
            #pragma unroll
            for (int mf = 0; mf < 2; mf++)
                #pragma unroll
                for (int nf = 0; nf < 4; nf++) {
                    MMA16816(acc[mf][nf], a[mf], bh2[nf]);
                    MMA16816(acc[mf][nf], a[mf], bl2[nf]);
                }
            #pragma unroll
            for (int mf = 0; mf < 2; mf++) {
                int row = wm * 32 + mf * 16 + a_row_l;
                uint32_t addr = aAl + sw128((uint32_t)(row * 128 + ks * 32 + a_cb_l));
                LDSM_X4(a[mf][0], a[mf][1], a[mf][2], a[mf][3], addr);
            }
            #pragma unroll
            for (int mf = 0; mf < 2; mf++)
                #pragma unroll
                for (int nf = 0; nf < 4; nf++)
                    MMA16816(acc[mf][nf], a[mf], bh2[nf]);
        }
    }

    // Epilogue: write bf16 hi/lo x into [B,L,D]
    int b = bh >> 4, h = bh & 15;
    int r0 = lane >> 2;
    int c0 = (lane & 3) * 2;

    #pragma unroll
    for (int mf = 0; mf < 2; mf++) {
        #pragma unroll
        for (int e2 = 0; e2 < 2; e2++) {
            int q = q0 + wm * 32 + mf * 16 + r0 + e2 * 8;
            #pragma unroll
            for (int nf = 0; nf < 4; nf++) {
                int hd = wn * 32 + nf * 8 + c0;
                float v0 = acc[mf][nf][e2*2+0];
                float v1 = acc[mf][nf][e2*2+1];
                float h0 = __bfloat162float(__float2bfloat16(v0));
                float h1 = __bfloat162float(__float2bfloat16(v1));
                size_t idx = ((size_t)(b * L_ + q)) * D_ + h * HD_ + hd;
                *(uint32_t*)(g_xh + idx) = pack_bf2(v0, v1);
                *(uint32_t*)(g_xl + idx) = pack_bf2(v0 - h0, v1 - h1);
            }
        }
    }
}

// ---------------------------------------------------------------------------
extern "C" void kernel_launch(void* const* d_in, const int* in_sizes, int n_in,
                              void* d_out, int out_size)
{
    const float* query = (const float*)d_in[0];
    const float* abias = (const float*)d_in[1];
    const float* Wq    = (const float*)d_in[2];
    const float* bq    = (const float*)d_in[3];
    const float* Wk    = (const float*)d_in[4];
    const float* bk    = (const float*)d_in[5];
    const float* Wv    = (const float*)d_in[6];
    const float* bv    = (const float*)d_in[7];
    const float* Wo    = (const float*)d_in[8];
    const float* bo    = (const float*)d_in[9];

    float* out  = (float*)d_out;
    float* ans  = out;                              // [B,L,D]
    float* attn = out + (size_t)M_ * D_;            // [B,H,L,L]

    cudaFuncSetAttribute(logits_mma, cudaFuncAttributeMaxDynamicSharedMemorySize, LG_SMEM);
    cudaFuncSetAttribute(proj_mma,   cudaFuncAttributeMaxDynamicSharedMemorySize, PJ_SMEM);
    cudaFuncSetAttribute(av_fused,   cudaFuncAttributeMaxDynamicSharedMemorySize, AV_SMEM);

    __nv_bfloat16 *p_inh, *p_inl, *p_wth, *p_wtl, *p_xh, *p_xl;
    cudaGetSymbolAddress((void**)&p_inh, g_inh);
    cudaGetSymbolAddress((void**)&p_inl, g_inl);
    cudaGetSymbolAddress((void**)&p_wth, g_wth);
    cudaGetSymbolAddress((void**)&p_wtl, g_wtl);
    cudaGetSymbolAddress((void**)&p_xh, g_xh);
    cudaGetSymbolAddress((void**)&p_xl, g_xl);

    split_x<<<M_ * D_ / 1024, 256>>>(query);
    dim3 gwt(D_ / 64, D_ / 64);
    split_wt<<<gwt, 256>>>(Wq, 0);
    split_wt<<<gwt, 256>>>(Wk, 1);
    split_wt<<<gwt, 256>>>(Wv, 2);
    split_wt<<<gwt, 256>>>(Wo, 3);

    dim3 gproj(D_ / 128, M_ / 128);
    proj_mma<<<gproj, 256, PJ_SMEM>>>(p_inh, p_inl, p_wth + 0 * (size_t)D_ * D_,
                                      p_wtl + 0 * (size_t)D_ * D_, bq, nullptr, 0);
    proj_mma<<<gproj, 256, PJ_SMEM>>>(p_inh, p_inl, p_wth + 1 * (size_t)D_ * D_,
                                      p_wtl + 1 * (size_t)D_ * D_, bk, nullptr, 1);
    proj_mma<<<gproj, 256, PJ_SMEM>>>(p_inh, p_inl, p_wth + 2 * (size_t)D_ * D_,
                                      p_wtl + 2 * (size_t)D_ * D_, bv, nullptr, 2);

    logits_mma<<<dim3(L_ / 128, L_ / 128, B_ * H_), 256, LG_SMEM>>>(abias, attn);

    combine_stats<<<NBH * L_ / 256, 256>>>();

    av_fused<<<dim3(L_ / 128, B_ * H_), 256, AV_SMEM>>>(attn);

    proj_mma<<<gproj, 256, PJ_SMEM>>>(p_xh, p_xl, p_wth + 3 * (size_t)D_ * D_,
                                      p_wtl + 3 * (size_t)D_ * D_, bo, ans, 3);
}

// round 7
// speedup vs baseline: 2.5917x; 1.3431x over previous
#include <cuda_runtime.h>
#include <cuda_bf16.h>
#include <cstdint>

#define B_  2
#define L_  2048
#define D_  1024
#define H_  16
#define HD_ 64
#define M_  (B_ * L_)
#define NBH (B_ * H_)   // 32
#define KT_ (L_ / 128)  // 16 k-tiles per row in logits

// ---------------------------------------------------------------------------
// Scratch (device globals)
// ---------------------------------------------------------------------------
__device__ __nv_bfloat16 g_inh[M_ * D_], g_inl[M_ * D_];
__device__ __nv_bfloat16 g_wth[4][D_ * D_], g_wtl[4][D_ * D_];
__device__ __nv_bfloat16 g_qh[B_ * H_ * L_ * HD_], g_ql[B_ * H_ * L_ * HD_];
__device__ __nv_bfloat16 g_kh[B_ * H_ * L_ * HD_], g_kl[B_ * H_ * L_ * HD_];
__device__ __nv_bfloat16 g_vh[B_ * H_ * L_ * HD_], g_vl[B_ * H_ * L_ * HD_];
__device__ __nv_bfloat16 g_xh[M_ * D_], g_xl[M_ * D_];
__device__ float g_pmax[NBH * L_ * KT_];
__device__ float g_psum[NBH * L_ * KT_];
__device__ float g_rm[NBH * L_];
__device__ float g_ri[NBH * L_];

__device__ __forceinline__ uint32_t smem_u32(const void* p) {
    uint32_t a;
    asm("{ .reg .u64 t; cvta.to.shared.u64 t, %1; cvt.u32.u64 %0, t; }"
        : "=r"(a) : "l"(p));
    return a;
}

__device__ __forceinline__ uint32_t sw128(uint32_t off) {
    return off ^ ((off >> 3) & 0x70);
}

__device__ __forceinline__ uint32_t pack_bf2(float a, float b) {
    return (uint32_t)__bfloat16_as_ushort(__float2bfloat16(a))
         | ((uint32_t)__bfloat16_as_ushort(__float2bfloat16(b)) << 16);
}

#define LDSM_X4(r0,r1,r2,r3,addr) \
    asm volatile("ldmatrix.sync.aligned.m8n8.x4.shared.b16 {%0,%1,%2,%3}, [%4];" \
        : "=r"(r0), "=r"(r1), "=r"(r2), "=r"(r3) : "r"(addr))

#define LDSM_X2(r0,r1,addr) \
    asm volatile("ldmatrix.sync.aligned.m8n8.x2.shared.b16 {%0,%1}, [%2];" \
        : "=r"(r0), "=r"(r1) : "r"(addr))

#define LDSM_X2T(r0,r1,addr) \
    asm volatile("ldmatrix.sync.aligned.m8n8.x2.trans.shared.b16 {%0,%1}, [%2];" \
        : "=r"(r0), "=r"(r1) : "r"(addr))

#define MMA16816(acc, af, bf) \
    asm volatile("mma.sync.aligned.m16n8k16.row.col.f32.bf16.bf16.f32 " \
        "{%0,%1,%2,%3}, {%4,%5,%6,%7}, {%8,%9}, {%0,%1,%2,%3};" \
        : "+f"((acc)[0]), "+f"((acc)[1]), "+f"((acc)[2]), "+f"((acc)[3]) \
        : "r"((af)[0]), "r"((af)[1]), "r"((af)[2]), "r"((af)[3]), \
          "r"((bf)[0]), "r"((bf)[1]))

#define CP16(dst_u32, src_ptr) \
    asm volatile("cp.async.cg.shared.global [%0], [%1], 16;" \
        :: "r"(dst_u32), "l"(src_ptr))
#define CP_COMMIT() asm volatile("cp.async.commit_group;" ::: "memory")
#define CP_WAIT0()  asm volatile("cp.async.wait_group 0;" ::: "memory")

// ---------------------------------------------------------------------------
// Prep kernels
// ---------------------------------------------------------------------------
__global__ void split_x(const float* __restrict__ X)
{
    int i = (blockIdx.x * 256 + threadIdx.x) * 4;
    float4 v = *(const float4*)(X + i);
    float h0 = __bfloat162float(__float2bfloat16(v.x));
    float h1 = __bfloat162float(__float2bfloat16(v.y));
    float h2 = __bfloat162float(__float2bfloat16(v.z));
    float h3 = __bfloat162float(__float2bfloat16(v.w));
    *(uint2*)(g_inh + i) = make_uint2(pack_bf2(v.x, v.y), pack_bf2(v.z, v.w));
    *(uint2*)(g_inl + i) = make_uint2(pack_bf2(v.x - h0, v.y - h1), pack_bf2(v.z - h2, v.w - h3));
}

__global__ void split_wt(const float* __restrict__ W, int widx)
{
    __shared__ float ts[64][65];
    int tid = threadIdx.x;
    int r0 = blockIdx.x * 64;
    int c0 = blockIdx.y * 64;

    #pragma unroll
    for (int i = 0; i < 4; i++) {
        int u = tid + i * 256;
        int row = u >> 4, c4 = (u & 15) * 4;
        float4 v = *(const float4*)(W + (size_t)(r0 + row) * D_ + c0 + c4);
        ts[row][c4+0] = v.x; ts[row][c4+1] = v.y;
        ts[row][c4+2] = v.z; ts[row][c4+3] = v.w;
    }
    __syncthreads();

    __nv_bfloat16* dh = g_wth[widx];
    __nv_bfloat16* dl = g_wtl[widx];
    #pragma unroll
    for (int i = 0; i < 4; i++) {
        int u = tid + i * 256;
        int nrow = u >> 4, k4 = (u & 15) * 4;
        float v0 = ts[k4+0][nrow], v1 = ts[k4+1][nrow];
        float v2 = ts[k4+2][nrow], v3 = ts[k4+3][nrow];
        float h0 = __bfloat162float(__float2bfloat16(v0));
        float h1 = __bfloat162float(__float2bfloat16(v1));
        float h2 = __bfloat162float(__float2bfloat16(v2));
        float h3 = __bfloat162float(__float2bfloat16(v3));
        size_t off = (size_t)(c0 + nrow) * D_ + r0 + k4;
        *(uint2*)(dh + off) = make_uint2(pack_bf2(v0, v1), pack_bf2(v2, v3));
        *(uint2*)(dl + off) = make_uint2(pack_bf2(v0-h0, v1-h1), pack_bf2(v2-h2, v3-h3));
    }
}

// ---------------------------------------------------------------------------
// proj_mma: double-buffered cp.async pipeline.
// Buffer layout (per buf): Xh@0, Xl@16K, Wh@32K, Wl@48K  (64KB); 2 buffers.
// ---------------------------------------------------------------------------
#define PJ_BUF  65536
#define PJ_SMEM (2 * PJ_BUF + 1024)

__global__ void __launch_bounds__(256)
proj_mma(const __nv_bfloat16* __restrict__ Xh, const __nv_bfloat16* __restrict__ Xl,
         const __nv_bfloat16* __restrict__ Wth, const __nv_bfloat16* __restrict__ Wtl,
         const float* __restrict__ bias, float* __restrict__ Yout, int mode)
{
    extern __shared__ char smem_raw[];
    uint32_t raw = smem_u32(smem_raw);
    uint32_t base = (raw + 1023u) & ~1023u;

    int tid = threadIdx.x;
    int wid = tid >> 5, lane = tid & 31;
    int n0 = blockIdx.x * 128;
    int m0 = blockIdx.y * 128;
    int wm = wid >> 2, wn = wid & 3;

    float acc[4][4][4] = {};

    int a_row_l = lane & 15;
    int a_cb_l  = (lane >> 4) << 4;

    auto stage = [&](int kc, int buf) {
        uint32_t bb = base + (uint32_t)buf * PJ_BUF;
        int k0 = kc * 64;
        #pragma unroll
        for (int i = 0; i < 4; i++) {
            int u = tid + i * 256;
            int row = u >> 3, unit = u & 7;
            uint32_t dst = sw128((uint32_t)(row * 128 + unit * 16));
            size_t xoff = (size_t)(m0 + row) * D_ + k0 + unit * 8;
            size_t woff = (size_t)(n0 + row) * D_ + k0 + unit * 8;
            CP16(bb + dst,          Xh  + xoff);
            CP16(bb + 16384 + dst,  Xl  + xoff);
            CP16(bb + 32768 + dst,  Wth + woff);
            CP16(bb + 49152 + dst,  Wtl + woff);
        }
        CP_COMMIT();
    };

    stage(0, 0);

    for (int kc = 0; kc < 16; kc++) {
        CP_WAIT0();
        __syncthreads();
        if (kc + 1 < 16) stage(kc + 1, (kc + 1) & 1);

        uint32_t bb = base + (uint32_t)(kc & 1) * PJ_BUF;
        uint32_t aXh = bb, aXl = bb + 16384, aWh = bb + 32768, aWl = bb + 49152;

        #pragma unroll
        for (int ks = 0; ks < 4; ks++) {
            uint32_t a[4][4], bh[4][2], bl[4][2];
            #pragma unroll
            for (int mf = 0; mf < 4; mf++) {
                int row = wm * 64 + mf * 16 + a_row_l;
                uint32_t addr = aXh + sw128((uint32_t)(row * 128 + ks * 32 + a_cb_l));
                LDSM_X4(a[mf][0], a[mf][1], a[mf][2], a[mf][3], addr);
            }
            #pragma unroll
            for (int nf = 0; nf < 4; nf++) {
                int row = wn * 32 + nf * 8 + (lane & 7);
                uint32_t boff = sw128((uint32_t)(row * 128 + ks * 32 + (((lane >> 3) & 1) << 4)));
                LDSM_X2(bh[nf][0], bh[nf][1], aWh + boff);
                LDSM_X2(bl[nf][0], bl[nf][1], aWl + boff);
            }
            #pragma unroll
            for (int mf = 0; mf < 4; mf++)
                #pragma unroll
                for (int nf = 0; nf < 4; nf++) {
                    MMA16816(acc[mf][nf], a[mf], bh[nf]);
                    MMA16816(acc[mf][nf], a[mf], bl[nf]);
                }
            #pragma unroll
            for (int mf = 0; mf < 4; mf++) {
                int row = wm * 64 + mf * 16 + a_row_l;
                uint32_t addr = aXl + sw128((uint32_t)(row * 128 + ks * 32 + a_cb_l));
                LDSM_X4(a[mf][0], a[mf][1], a[mf][2], a[mf][3], addr);
            }
            #pragma unroll
            for (int mf = 0; mf < 4; mf++)
                #pragma unroll
                for (int nf = 0; nf < 4; nf++)
                    MMA16816(acc[mf][nf], a[mf], bh[nf]);
        }
        __syncthreads();
    }

    int r0 = lane >> 2;
    int c0 = (lane & 3) * 2;
    __nv_bfloat16* dsth = (mode == 0) ? g_qh : (mode == 1) ? g_kh : g_vh;
    __nv_bfloat16* dstl = (mode == 0) ? g_ql : (mode == 1) ? g_kl : g_vl;

    #pragma unroll
    for (int mf = 0; mf < 4; mf++) {
        #pragma unroll
        for (int e2 = 0; e2 < 2; e2++) {
            int r = m0 + wm * 64 + mf * 16 + r0 + e2 * 8;
            #pragma unroll
            for (int nf = 0; nf < 4; nf++) {
                int c = n0 + wn * 32 + nf * 8 + c0;
                float v0 = acc[mf][nf][e2*2+0] + bias[c];
                float v1 = acc[mf][nf][e2*2+1] + bias[c+1];
                if (mode < 3) {
                    int b = r >> 11, l = r & 2047;
                    int h = c >> 6, hd = c & 63;
                    size_t idx = (((size_t)(b * H_ + h)) * L_ + l) * HD_ + hd;
                    float h0 = __bfloat162float(__float2bfloat16(v0));
                    float h1 = __bfloat162float(__float2bfloat16(v1));
                    *(uint32_t*)(dsth + idx) = pack_bf2(v0, v1);
                    *(uint32_t*)(dstl + idx) = pack_bf2(v0 - h0, v1 - h1);
                } else {
                    *(float2*)(Yout + (size_t)r * D_ + c) = make_float2(v0, v1);
                }
            }
        }
    }
}

// ---------------------------------------------------------------------------
// Logits + per-tile softmax stats (unchanged from R6)
// ---------------------------------------------------------------------------
#define LG_TILE   16384
#define LG_SMEM   (4 * LG_TILE + 1024)

__global__ void __launch_bounds__(256)
logits_mma(const float* __restrict__ abias, float* __restrict__ attn)
{
    extern __shared__ char smem_raw[];
    uint32_t raw = smem_u32(smem_raw);
    uint32_t base = (raw + 1023u) & ~1023u;
    char* smem = smem_raw + (base - raw);

    int tid  = threadIdx.x;
    int wid  = tid >> 5;
    int lane = tid & 31;
    int bh = blockIdx.z;
    int q0 = blockIdx.y * 128;
    int k0 = blockIdx.x * 128;

    const char* srcs[4] = {
        (const char*)(g_qh + ((size_t)bh * L_ + q0) * HD_),
        (const char*)(g_ql + ((size_t)bh * L_ + q0) * HD_),
        (const char*)(g_kh + ((size_t)bh * L_ + k0) * HD_),
        (const char*)(g_kl + ((size_t)bh * L_ + k0) * HD_)
    };
    #pragma unroll
    for (int t = 0; t < 4; t++) {
        uint32_t dst = base + t * LG_TILE;
        const char* s = srcs[t];
        #pragma unroll
        for (int u = 0; u < 4; u++) {
            uint32_t off = (uint32_t)(tid + u * 256) * 16u;
            CP16(dst + sw128(off), s + off);
        }
    }
    CP_COMMIT();
    CP_WAIT0();
    __syncthreads();

    int wm = wid >> 2;
    int wn = wid & 3;

    float acc[4][4][4] = {};

    int a_row_l = lane & 15;
    int a_cb_l  = (lane >> 4) << 4;
    int b_row_l = lane & 7;
    int b_cb_l  = ((lane >> 3) & 1) << 4;

    #pragma unroll
    for (int pass = 0; pass < 3; pass++) {
        uint32_t aBase = base + ((pass == 2) ? LG_TILE : 0);
        uint32_t bBase = base + ((pass == 1) ? 3 * LG_TILE : 2 * LG_TILE);

        #pragma unroll
        for (int ks = 0; ks < 4; ks++) {
            uint32_t a[4][4];
            #pragma unroll
            for (int mf = 0; mf < 4; mf++) {
                int row = wm * 64 + mf * 16 + a_row_l;
                uint32_t addr = aBase + sw128((uint32_t)(row * 128 + ks * 32 + a_cb_l));
                LDSM_X4(a[mf][0], a[mf][1], a[mf][2], a[mf][3], addr);
            }
            uint32_t b[4][2];
            #pragma unroll
            for (int nf = 0; nf < 4; nf++) {
                int row = wn * 32 + nf * 8 + b_row_l;
                uint32_t addr = bBase + sw128((uint32_t)(row * 128 + ks * 32 + b_cb_l));
                LDSM_X2(b[nf][0], b[nf][1], addr);
            }
            #pragma unroll
            for (int mf = 0; mf < 4; mf++)
                #pragma unroll
                for (int nf = 0; nf < 4; nf++)
                    MMA16816(acc[mf][nf], a[mf], b[nf]);
        }
    }

    int b = bh >> 4;
    size_t attn_base = (size_t)bh * L_ * L_;
    int qbase = q0 + wm * 64;
    int kbase = k0 + wn * 32;
    int r0 = lane >> 2;
    int c0 = (lane & 3) * 2;

    #pragma unroll
    for (int mf = 0; mf < 4; mf++) {
        #pragma unroll
        for (int e2 = 0; e2 < 2; e2++) {
            int q = qbase + mf * 16 + r0 + e2 * 8;
            const float* brow = abias + ((size_t)b * L_ + q) * L_;
            float* orow = attn + attn_base + (size_t)q * L_;
            #pragma unroll
            for (int nf = 0; nf < 4; nf++) {
                int k = kbase + nf * 8 + c0;
                float2 bb = *(const float2*)(brow + k);
                float v0 = acc[mf][nf][e2*2+0] * 0.125f + bb.x;
                float v1 = acc[mf][nf][e2*2+1] * 0.125f + bb.y;
                acc[mf][nf][e2*2+0] = v0;
                acc[mf][nf][e2*2+1] = v1;
                *(float2*)(orow + k) = make_float2(v0, v1);
            }
        }
    }

    __syncthreads();
    float* smax = (float*)smem;
    float* ssum = smax + 512;

    #pragma unroll
    for (int mf = 0; mf < 4; mf++) {
        #pragma unroll
        for (int e2 = 0; e2 < 2; e2++) {
            float rm = -3.4e38f;
            #pragma unroll
            for (int nf = 0; nf < 4; nf++)
                rm = fmaxf(rm, fmaxf(acc[mf][nf][e2*2], acc[mf][nf][e2*2+1]));
            rm = fmaxf(rm, __shfl_xor_sync(~0u, rm, 1));
            rm = fmaxf(rm, __shfl_xor_sync(~0u, rm, 2));
            int rw = wm * 64 + mf * 16 + e2 * 8 + r0;
            if ((lane & 3) == 0) smax[rw * 4 + wn] = rm;
        }
    }
    __syncthreads();
    #pragma unroll
    for (int mf = 0; mf < 4; mf++) {
        #pragma unroll
        for (int e2 = 0; e2 < 2; e2++) {
            int rw = wm * 64 + mf * 16 + e2 * 8 + r0;
            float tm = fmaxf(fmaxf(smax[rw*4+0], smax[rw*4+1]),
                             fmaxf(smax[rw*4+2], smax[rw*4+3]));
            float s = 0.f;
            #pragma unroll
            for (int nf = 0; nf < 4; nf++)
                s += __expf(acc[mf][nf][e2*2] - tm) + __expf(acc[mf][nf][e2*2+1] - tm);
            s += __shfl_xor_sync(~0u, s, 1);
            s += __shfl_xor_sync(~0u, s, 2);
            if ((lane & 3) == 0) ssum[rw * 4 + wn] = s;
        }
    }
    __syncthreads();
    if (tid < 128) {
        float tm = fmaxf(fmaxf(smax[tid*4+0], smax[tid*4+1]),
                         fmaxf(smax[tid*4+2], smax[tid*4+3]));
        float s = ssum[tid*4+0] + ssum[tid*4+1] + ssum[tid*4+2] + ssum[tid*4+3];
        size_t sidx = ((size_t)bh * L_ + q0 + tid) * KT_ + blockIdx.x;
        g_pmax[sidx] = tm;
        g_psum[sidx] = s;
    }
}

// ---------------------------------------------------------------------------
__global__ void combine_stats()
{
    int row = blockIdx.x * 256 + threadIdx.x;
    const float* pm = g_pmax + (size_t)row * KT_;
    const float* ps = g_psum + (size_t)row * KT_;
    float M = -3.4e38f;
    #pragma unroll
    for (int t = 0; t < KT_; t++) M = fmaxf(M, pm[t]);
    float S = 0.f;
    #pragma unroll
    for (int t = 0; t < KT_; t++) S += ps[t] * __expf(pm[t] - M);
    g_rm[row] = M;
    g_ri[row] = 1.0f / S;
}

// ---------------------------------------------------------------------------
// av_fused: double-buffered pipeline. V via cp.async; A via register prefetch
// (needs exp transform + attn write-back). Buffer: Ah@0, Al@16K, Vh@32K,
// Vl@40K (48KB); 2 buffers + stats.
// ---------------------------------------------------------------------------
#define AV_BUF  49152
#define AV_SMEM (2 * AV_BUF + 2048)

__global__ void __launch_bounds__(256)
av_fused(float* __restrict__ attn)
{
    extern __shared__ char smem_raw[];
    uint32_t raw = smem_u32(smem_raw);
    uint32_t base = (raw + 1023u) & ~1023u;
    char* smem = smem_raw + (base - raw);

    float* s_m  = (float*)(smem + 2 * AV_BUF);   // [128]
    float* s_ri = s_m + 128;                     // [128]

    int tid = threadIdx.x;
    int wid = tid >> 5, lane = tid & 31;
    int bh = blockIdx.y;
    int q0 = blockIdx.x * 128;
    int wm = wid >> 1;
    int wn = wid & 1;

    float* A = attn + (size_t)bh * L_ * L_;
    const __nv_bfloat16* Vh = g_vh + (size_t)bh * L_ * HD_;
    const __nv_bfloat16* Vl = g_vl + (size_t)bh * L_ * HD_;

    if (tid < 128) {
        size_t r = (size_t)bh * L_ + q0 + tid;
        s_m[tid]  = g_rm[r];
        s_ri[tid] = g_ri[r];
    }

    // per-thread A staging geometry (8 float4 covering 128x64 fp32)
    int st_row[8], st_f4[8];
    #pragma unroll
    for (int i = 0; i < 8; i++) {
        int u = tid + i * 256;
        st_row[i] = u >> 4;
        st_f4[i]  = (u & 15) * 4;
    }

    auto issueV = [&](int kc, int buf) {
        uint32_t bb = base + (uint32_t)buf * AV_BUF;
        int k0 = kc * 64;
        #pragma unroll
        for (int i = 0; i < 2; i++) {
            int u = tid + i * 256;
            int row = u >> 3, unit = u & 7;
            uint32_t dst = sw128((uint32_t)(row * 128 + unit * 16));
            size_t off = (size_t)(k0 + row) * HD_ + unit * 8;
            CP16(bb + 32768 + dst, Vh + off);
            CP16(bb + 40960 + dst, Vl + off);
        }
        CP_COMMIT();
    };

    float4 apf[8];
    auto loadA = [&](int kc) {
        int k0 = kc * 64;
        #pragma unroll
        for (int i = 0; i < 8; i++)
            apf[i] = *(const float4*)(A + (size_t)(q0 + st_row[i]) * L_ + k0 + st_f4[i]);
    };

    auto xformA = [&](int kc, int buf) {
        char* bb = smem + buf * AV_BUF;
        int k0 = kc * 64;
        #pragma unroll
        for (int i = 0; i < 8; i++) {
            int row = st_row[i], f4 = st_f4[i];
            float m = s_m[row], ri = s_ri[row];
            float4 t = apf[i];
            t.x = __expf(t.x - m) * ri;
            t.y = __expf(t.y - m) * ri;
            t.z = __expf(t.z - m) * ri;
            t.w = __expf(t.w - m) * ri;
            *(float4*)(A + (size_t)(q0 + row) * L_ + k0 + f4) = t;
            float h0 = __bfloat162float(__float2bfloat16(t.x));
            float h1 = __bfloat162float(__float2bfloat16(t.y));
            float h2 = __bfloat162float(__float2bfloat16(t.z));
            float h3 = __bfloat162float(__float2bfloat16(t.w));
            uint32_t so = sw128((uint32_t)(row * 128 + f4 * 2));
            *(uint2*)(bb + so)         = make_uint2(pack_bf2(t.x, t.y), pack_bf2(t.z, t.w));
            *(uint2*)(bb + 16384 + so) = make_uint2(pack_bf2(t.x - h0, t.y - h1),
                                                    pack_bf2(t.z - h2, t.w - h3));
        }
    };

    float acc[2][4][4] = {};
    int a_row_l = lane & 15;
    int a_cb_l  = (lane >> 4) << 4;

    // prologue: chunk 0
    issueV(0, 0);
    loadA(0);
    __syncthreads();            // s_m/s_ri visible
    xformA(0, 0);

    for (int kc = 0; kc < 32; kc++) {
        CP_WAIT0();
        __syncthreads();        // buf[kc&1] fully staged; prior compute done
        int nb = (kc + 1) & 1;
        if (kc + 1 < 32) {
            issueV(kc + 1, nb);
            loadA(kc + 1);
        }

        uint32_t bb = base + (uint32_t)(kc & 1) * AV_BUF;
        uint32_t aAh = bb, aAl = bb + 16384, aVh = bb + 32768, aVl = bb + 40960;

        #pragma unroll
        for (int ks = 0; ks < 4; ks++) {
            uint32_t a[2][4], bh2[4][2], bl2[4][2];
            #pragma unroll
            for (int mf = 0; mf < 2; mf++) {
                int row = wm * 32 + mf * 16 + a_row_l;
                uint32_t addr = aAh + sw128((uint32_t)(row * 128 + ks * 32 + a_cb_l));
                LDSM_X4(a[mf][0], a[mf][1], a[mf][2], a[mf][3], addr);
            }
            #pragma unroll
            for (int nf = 0; nf < 4; nf++) {
                int row = ks * 16 + (lane & 15);
                uint32_t boff = sw128((uint32_t)(row * 128 + wn * 64 + nf * 16));
                LDSM_X2T(bh2[nf][0], bh2[nf][1], aVh + boff);
                LDSM_X2T(bl2[nf][0], bl2[nf][1], aVl + boff);
            }
            #pragma unroll
            for (int mf = 0; mf < 2; mf++)
                #pragma unroll
                for (int nf = 0; nf < 4; nf++) {
                    MMA16816(acc[mf][nf], a[mf], bh2[nf]);
                    MMA16816(acc[mf][nf], a[mf], bl2[nf]);
                }
            #pragma unroll
            for (int mf = 0; mf < 2; mf++) {
                int row = wm * 32 + mf * 16 + a_row_l;
                uint32_t addr = aAl + sw128((uint32_t)(row * 128 + ks * 32 + a_cb_l));
                LDSM_X4(a[mf][0], a[mf][1], a[mf][2], a[mf][3], addr);
            }
            #pragma unroll
            for (int mf = 0; mf < 2; mf++)
                #pragma unroll
                for (int nf = 0; nf < 4; nf++)
                    MMA16816(acc[mf][nf], a[mf], bh2[nf]);
        }

        if (kc + 1 < 32) xformA(kc + 1, nb);
        __syncthreads();
    }

    int b = bh >> 4, h = bh & 15;
    int r0 = lane >> 2;
    int c0 = (lane & 3) * 2;

    #pragma unroll
    for (int mf = 0; mf < 2; mf++) {
        #pragma unroll
        for (int e2 = 0; e2 < 2; e2++) {
            int q = q0 + wm * 32 + mf * 16 + r0 + e2 * 8;
            #pragma unroll
            for (int nf = 0; nf < 4; nf++) {
                int hd = wn * 32 + nf * 8 + c0;
                float v0 = acc[mf][nf][e2*2+0];
                float v1 = acc[mf][nf][e2*2+1];
                float h0 = __bfloat162float(__float2bfloat16(v0));
                float h1 = __bfloat162float(__float2bfloat16(v1));
                size_t idx = ((size_t)(b * L_ + q)) * D_ + h * HD_ + hd;
                *(uint32_t*)(g_xh + idx) = pack_bf2(v0, v1);
                *(uint32_t*)(g_xl + idx) = pack_bf2(v0 - h0, v1 - h1);
            }
        }
    }
}

// ---------------------------------------------------------------------------
extern "C" void kernel_launch(void* const* d_in, const int* in_sizes, int n_in,
                              void* d_out, int out_size)
{
    const float* query = (const float*)d_in[0];
    const float* abias = (const float*)d_in[1];
    const float* Wq    = (const float*)d_in[2];
    const float* bq    = (const float*)d_in[3];
    const float* Wk    = (const float*)d_in[4];
    const float* bk    = (const float*)d_in[5];
    const float* Wv    = (const float*)d_in[6];
    const float* bv    = (const float*)d_in[7];
    const float* Wo    = (const float*)d_in[8];
    const float* bo    = (const float*)d_in[9];

    float* out  = (float*)d_out;
    float* ans  = out;
    float* attn = out + (size_t)M_ * D_;

    cudaFuncSetAttribute(logits_mma, cudaFuncAttributeMaxDynamicSharedMemorySize, LG_SMEM);
    cudaFuncSetAttribute(proj_mma,   cudaFuncAttributeMaxDynamicSharedMemorySize, PJ_SMEM);
    cudaFuncSetAttribute(av_fused,   cudaFuncAttributeMaxDynamicSharedMemorySize, AV_SMEM);

    __nv_bfloat16 *p_inh, *p_inl, *p_wth, *p_wtl, *p_xh, *p_xl;
    cudaGetSymbolAddress((void**)&p_inh, g_inh);
    cudaGetSymbolAddress((void**)&p_inl, g_inl);
    cudaGetSymbolAddress((void**)&p_wth, g_wth);
    cudaGetSymbolAddress((void**)&p_wtl, g_wtl);
    cudaGetSymbolAddress((void**)&p_xh, g_xh);
    cudaGetSymbolAddress((void**)&p_xl, g_xl);

    split_x<<<M_ * D_ / 1024, 256>>>(query);
    dim3 gwt(D_ / 64, D_ / 64);
    split_wt<<<gwt, 256>>>(Wq, 0);
    split_wt<<<gwt, 256>>>(Wk, 1);
    split_wt<<<gwt, 256>>>(Wv, 2);
    split_wt<<<gwt, 256>>>(Wo, 3);

    dim3 gproj(D_ / 128, M_ / 128);
    proj_mma<<<gproj, 256, PJ_SMEM>>>(p_inh, p_inl, p_wth + 0 * (size_t)D_ * D_,
                                      p_wtl + 0 * (size_t)D_ * D_, bq, nullptr, 0);
    proj_mma<<<gproj, 256, PJ_SMEM>>>(p_inh, p_inl, p_wth + 1 * (size_t)D_ * D_,
                                      p_wtl + 1 * (size_t)D_ * D_, bk, nullptr, 1);
    proj_mma<<<gproj, 256, PJ_SMEM>>>(p_inh, p_inl, p_wth + 2 * (size_t)D_ * D_,
                                      p_wtl + 2 * (size_t)D_ * D_, bv, nullptr, 2);

    logits_mma<<<dim3(L_ / 128, L_ / 128, B_ * H_), 256, LG_SMEM>>>(abias, attn);

    combine_stats<<<NBH * L_ / 256, 256>>>();

    av_fused<<<dim3(L_ / 128, B_ * H_), 256, AV_SMEM>>>(attn);

    proj_mma<<<gproj, 256, PJ_SMEM>>>(p_xh, p_xl, p_wth + 3 * (size_t)D_ * D_,
                                      p_wtl + 3 * (size_t)D_ * D_, bo, ans, 3);
}

// round 8
// speedup vs baseline: 2.6408x; 1.0189x over previous
#include <cuda_runtime.h>
#include <cuda_bf16.h>
#include <cstdint>

#define B_  2
#define L_  2048
#define D_  1024
#define H_  16
#define HD_ 64
#define M_  (B_ * L_)
#define NBH (B_ * H_)   // 32
#define KT_ (L_ / 128)  // 16 k-tiles per row in logits

// ---------------------------------------------------------------------------
// Scratch (device globals)
// ---------------------------------------------------------------------------
__device__ __nv_bfloat16 g_inh[M_ * D_], g_inl[M_ * D_];
__device__ __nv_bfloat16 g_wth[4][D_ * D_], g_wtl[4][D_ * D_];
__device__ __nv_bfloat16 g_qh[B_ * H_ * L_ * HD_], g_ql[B_ * H_ * L_ * HD_];
__device__ __nv_bfloat16 g_kh[B_ * H_ * L_ * HD_], g_kl[B_ * H_ * L_ * HD_];
__device__ __nv_bfloat16 g_vh[B_ * H_ * L_ * HD_], g_vl[B_ * H_ * L_ * HD_];
__device__ __nv_bfloat16 g_xh[M_ * D_], g_xl[M_ * D_];
__device__ float g_pmax[NBH * L_ * KT_];
__device__ float g_psum[NBH * L_ * KT_];
__device__ float g_rm[NBH * L_];
__device__ float g_ri[NBH * L_];

__device__ __forceinline__ uint32_t smem_u32(const void* p) {
    uint32_t a;
    asm("{ .reg .u64 t; cvta.to.shared.u64 t, %1; cvt.u32.u64 %0, t; }"
        : "=r"(a) : "l"(p));
    return a;
}

__device__ __forceinline__ uint32_t sw128(uint32_t off) {
    return off ^ ((off >> 3) & 0x70);
}

__device__ __forceinline__ uint32_t pack_bf2(float a, float b) {
    return (uint32_t)__bfloat16_as_ushort(__float2bfloat16(a))
         | ((uint32_t)__bfloat16_as_ushort(__float2bfloat16(b)) << 16);
}

#define LDSM_X4(r0,r1,r2,r3,addr) \
    asm volatile("ldmatrix.sync.aligned.m8n8.x4.shared.b16 {%0,%1,%2,%3}, [%4];" \
        : "=r"(r0), "=r"(r1), "=r"(r2), "=r"(r3) : "r"(addr))

#define LDSM_X2(r0,r1,addr) \
    asm volatile("ldmatrix.sync.aligned.m8n8.x2.shared.b16 {%0,%1}, [%2];" \
        : "=r"(r0), "=r"(r1) : "r"(addr))

#define LDSM_X2T(r0,r1,addr) \
    asm volatile("ldmatrix.sync.aligned.m8n8.x2.trans.shared.b16 {%0,%1}, [%2];" \
        : "=r"(r0), "=r"(r1) : "r"(addr))

#define MMA16816(acc, af, bf) \
    asm volatile("mma.sync.aligned.m16n8k16.row.col.f32.bf16.bf16.f32 " \
        "{%0,%1,%2,%3}, {%4,%5,%6,%7}, {%8,%9}, {%0,%1,%2,%3};" \
        : "+f"((acc)[0]), "+f"((acc)[1]), "+f"((acc)[2]), "+f"((acc)[3]) \
        : "r"((af)[0]), "r"((af)[1]), "r"((af)[2]), "r"((af)[3]), \
          "r"((bf)[0]), "r"((bf)[1]))

#define CP16(dst_u32, src_ptr) \
    asm volatile("cp.async.cg.shared.global [%0], [%1], 16;" \
        :: "r"(dst_u32), "l"(src_ptr))
#define CP_COMMIT() asm volatile("cp.async.commit_group;" ::: "memory")
#define CP_WAIT0()  asm volatile("cp.async.wait_group 0;" ::: "memory")
#define CP_WAIT1()  asm volatile("cp.async.wait_group 1;" ::: "memory")

// ---------------------------------------------------------------------------
// Prep kernels
// ---------------------------------------------------------------------------
__global__ void split_x(const float* __restrict__ X)
{
    int i = (blockIdx.x * 256 + threadIdx.x) * 4;
    float4 v = *(const float4*)(X + i);
    float h0 = __bfloat162float(__float2bfloat16(v.x));
    float h1 = __bfloat162float(__float2bfloat16(v.y));
    float h2 = __bfloat162float(__float2bfloat16(v.z));
    float h3 = __bfloat162float(__float2bfloat16(v.w));
    *(uint2*)(g_inh + i) = make_uint2(pack_bf2(v.x, v.y), pack_bf2(v.z, v.w));
    *(uint2*)(g_inl + i) = make_uint2(pack_bf2(v.x - h0, v.y - h1), pack_bf2(v.z - h2, v.w - h3));
}

// merged: z selects which W
__global__ void split_wt(const float* __restrict__ W0, const float* __restrict__ W1,
                         const float* __restrict__ W2, const float* __restrict__ W3)
{
    __shared__ float ts[64][65];
    int widx = blockIdx.z;
    const float* W = (widx == 0) ? W0 : (widx == 1) ? W1 : (widx == 2) ? W2 : W3;
    int tid = threadIdx.x;
    int r0 = blockIdx.x * 64;
    int c0 = blockIdx.y * 64;

    #pragma unroll
    for (int i = 0; i < 4; i++) {
        int u = tid + i * 256;
        int row = u >> 4, c4 = (u & 15) * 4;
        float4 v = *(const float4*)(W + (size_t)(r0 + row) * D_ + c0 + c4);
        ts[row][c4+0] = v.x; ts[row][c4+1] = v.y;
        ts[row][c4+2] = v.z; ts[row][c4+3] = v.w;
    }
    __syncthreads();

    __nv_bfloat16* dh = g_wth[widx];
    __nv_bfloat16* dl = g_wtl[widx];
    #pragma unroll
    for (int i = 0; i < 4; i++) {
        int u = tid + i * 256;
        int nrow = u >> 4, k4 = (u & 15) * 4;
        float v0 = ts[k4+0][nrow], v1 = ts[k4+1][nrow];
        float v2 = ts[k4+2][nrow], v3 = ts[k4+3][nrow];
        float h0 = __bfloat162float(__float2bfloat16(v0));
        float h1 = __bfloat162float(__float2bfloat16(v1));
        float h2 = __bfloat162float(__float2bfloat16(v2));
        float h3 = __bfloat162float(__float2bfloat16(v3));
        size_t off = (size_t)(c0 + nrow) * D_ + r0 + k4;
        *(uint2*)(dh + off) = make_uint2(pack_bf2(v0, v1), pack_bf2(v2, v3));
        *(uint2*)(dl + off) = make_uint2(pack_bf2(v0-h0, v1-h1), pack_bf2(v2-h2, v3-h3));
    }
}

// ---------------------------------------------------------------------------
// Shared projection body (double-buffered cp.async pipeline)
// ---------------------------------------------------------------------------
#define PJ_BUF  65536
#define PJ_SMEM (2 * PJ_BUF + 1024)

__device__ __forceinline__ void proj_body(
    char* smem_raw,
    const __nv_bfloat16* __restrict__ Xh, const __nv_bfloat16* __restrict__ Xl,
    const __nv_bfloat16* __restrict__ Wth, const __nv_bfloat16* __restrict__ Wtl,
    const float* __restrict__ bias, float* __restrict__ Yout,
    int mode, int n0, int m0)
{
    uint32_t raw = smem_u32(smem_raw);
    uint32_t base = (raw + 1023u) & ~1023u;

    int tid = threadIdx.x;
    int wid = tid >> 5, lane = tid & 31;
    int wm = wid >> 2, wn = wid & 3;

    float acc[4][4][4] = {};

    int a_row_l = lane & 15;
    int a_cb_l  = (lane >> 4) << 4;

    auto stage = [&](int kc, int buf) {
        uint32_t bb = base + (uint32_t)buf * PJ_BUF;
        int k0 = kc * 64;
        #pragma unroll
        for (int i = 0; i < 4; i++) {
            int u = tid + i * 256;
            int row = u >> 3, unit = u & 7;
            uint32_t dst = sw128((uint32_t)(row * 128 + unit * 16));
            size_t xoff = (size_t)(m0 + row) * D_ + k0 + unit * 8;
            size_t woff = (size_t)(n0 + row) * D_ + k0 + unit * 8;
            CP16(bb + dst,          Xh  + xoff);
            CP16(bb + 16384 + dst,  Xl  + xoff);
            CP16(bb + 32768 + dst,  Wth + woff);
            CP16(bb + 49152 + dst,  Wtl + woff);
        }
        CP_COMMIT();
    };

    stage(0, 0);

    for (int kc = 0; kc < 16; kc++) {
        CP_WAIT0();
        __syncthreads();
        if (kc + 1 < 16) stage(kc + 1, (kc + 1) & 1);

        uint32_t bb = base + (uint32_t)(kc & 1) * PJ_BUF;
        uint32_t aXh = bb, aXl = bb + 16384, aWh = bb + 32768, aWl = bb + 49152;

        #pragma unroll
        for (int ks = 0; ks < 4; ks++) {
            uint32_t a[4][4], bh[4][2], bl[4][2];
            #pragma unroll
            for (int mf = 0; mf < 4; mf++) {
                int row = wm * 64 + mf * 16 + a_row_l;
                uint32_t addr = aXh + sw128((uint32_t)(row * 128 + ks * 32 + a_cb_l));
                LDSM_X4(a[mf][0], a[mf][1], a[mf][2], a[mf][3], addr);
            }
            #pragma unroll
            for (int nf = 0; nf < 4; nf++) {
                int row = wn * 32 + nf * 8 + (lane & 7);
                uint32_t boff = sw128((uint32_t)(row * 128 + ks * 32 + (((lane >> 3) & 1) << 4)));
                LDSM_X2(bh[nf][0], bh[nf][1], aWh + boff);
                LDSM_X2(bl[nf][0], bl[nf][1], aWl + boff);
            }
            #pragma unroll
            for (int mf = 0; mf < 4; mf++)
                #pragma unroll
                for (int nf = 0; nf < 4; nf++) {
                    MMA16816(acc[mf][nf], a[mf], bh[nf]);
                    MMA16816(acc[mf][nf], a[mf], bl[nf]);
                }
            #pragma unroll
            for (int mf = 0; mf < 4; mf++) {
                int row = wm * 64 + mf * 16 + a_row_l;
                uint32_t addr = aXl + sw128((uint32_t)(row * 128 + ks * 32 + a_cb_l));
                LDSM_X4(a[mf][0], a[mf][1], a[mf][2], a[mf][3], addr);
            }
            #pragma unroll
            for (int mf = 0; mf < 4; mf++)
                #pragma unroll
                for (int nf = 0; nf < 4; nf++)
                    MMA16816(acc[mf][nf], a[mf], bh[nf]);
        }
        __syncthreads();
    }

    int r0 = lane >> 2;
    int c0 = (lane & 3) * 2;
    __nv_bfloat16* dsth = (mode == 0) ? g_qh : (mode == 1) ? g_kh : g_vh;
    __nv_bfloat16* dstl = (mode == 0) ? g_ql : (mode == 1) ? g_kl : g_vl;

    #pragma unroll
    for (int mf = 0; mf < 4; mf++) {
        #pragma unroll
        for (int e2 = 0; e2 < 2; e2++) {
            int r = m0 + wm * 64 + mf * 16 + r0 + e2 * 8;
            #pragma unroll
            for (int nf = 0; nf < 4; nf++) {
                int c = n0 + wn * 32 + nf * 8 + c0;
                float v0 = acc[mf][nf][e2*2+0] + bias[c];
                float v1 = acc[mf][nf][e2*2+1] + bias[c+1];
                if (mode < 3) {
                    int b = r >> 11, l = r & 2047;
                    int h = c >> 6, hd = c & 63;
                    size_t idx = (((size_t)(b * H_ + h)) * L_ + l) * HD_ + hd;
                    float h0 = __bfloat162float(__float2bfloat16(v0));
                    float h1 = __bfloat162float(__float2bfloat16(v1));
                    *(uint32_t*)(dsth + idx) = pack_bf2(v0, v1);
                    *(uint32_t*)(dstl + idx) = pack_bf2(v0 - h0, v1 - h1);
                } else {
                    *(float2*)(Yout + (size_t)r * D_ + c) = make_float2(v0, v1);
                }
            }
        }
    }
}

// QKV merged kernel: z selects projection
__global__ void __launch_bounds__(256)
qkv_mma(const __nv_bfloat16* __restrict__ Xh, const __nv_bfloat16* __restrict__ Xl,
        const __nv_bfloat16* __restrict__ Whb, const __nv_bfloat16* __restrict__ Wlb,
        const float* __restrict__ bq, const float* __restrict__ bk,
        const float* __restrict__ bv)
{
    extern __shared__ char smem_raw[];
    int m = blockIdx.z;
    const float* bias = (m == 0) ? bq : (m == 1) ? bk : bv;
    proj_body(smem_raw, Xh, Xl,
              Whb + (size_t)m * D_ * D_, Wlb + (size_t)m * D_ * D_,
              bias, nullptr, m, blockIdx.x * 128, blockIdx.y * 128);
}

// O projection
__global__ void __launch_bounds__(256)
oproj_mma(const __nv_bfloat16* __restrict__ Xh, const __nv_bfloat16* __restrict__ Xl,
          const __nv_bfloat16* __restrict__ Wth, const __nv_bfloat16* __restrict__ Wtl,
          const float* __restrict__ bias, float* __restrict__ Yout)
{
    extern __shared__ char smem_raw[];
    proj_body(smem_raw, Xh, Xl, Wth, Wtl, bias, Yout, 3,
              blockIdx.x * 128, blockIdx.y * 128);
}

// ---------------------------------------------------------------------------
// Logits: persistent over 4 k-tiles. Q resident; K double-buffered cp.async;
// bias prefetched to SMEM (padded rows, 528B stride) overlapped with mma.
// SMEM: Q@0 (Qh,Ql 32K) | K0@32K | K1@64K | bias@96K (67.6K) | stats@164K
// ---------------------------------------------------------------------------
#define LGQ   0
#define LGK0  32768
#define LGK1  65536
#define LGB   98304
#define LGS   (LGB + 128 * 528)          // 165888
#define LG_SMEM (LGS + 4096 + 1024)

__global__ void __launch_bounds__(256)
logits_mma(const float* __restrict__ abias, float* __restrict__ attn)
{
    extern __shared__ char smem_raw[];
    uint32_t raw = smem_u32(smem_raw);
    uint32_t base = (raw + 1023u) & ~1023u;
    char* smem = smem_raw + (base - raw);

    int tid  = threadIdx.x;
    int wid  = tid >> 5;
    int lane = tid & 31;
    int bh  = blockIdx.z;
    int q0  = blockIdx.y * 128;
    int ktg = blockIdx.x * 4;
    int b   = bh >> 4;

    // --- stage Q (resident) + K(0): one group ---
    {
        const char* sQh = (const char*)(g_qh + ((size_t)bh * L_ + q0) * HD_);
        const char* sQl = (const char*)(g_ql + ((size_t)bh * L_ + q0) * HD_);
        int k0 = ktg * 128;
        const char* sKh = (const char*)(g_kh + ((size_t)bh * L_ + k0) * HD_);
        const char* sKl = (const char*)(g_kl + ((size_t)bh * L_ + k0) * HD_);
        #pragma unroll
        for (int i = 0; i < 4; i++) {
            int u = tid + i * 256;
            uint32_t off = (uint32_t)u * 16u, sw = sw128(off);
            CP16(base + LGQ + sw,          sQh + off);
            CP16(base + LGQ + 16384 + sw,  sQl + off);
            CP16(base + LGK0 + sw,         sKh + off);
            CP16(base + LGK0 + 16384 + sw, sKl + off);
        }
        CP_COMMIT();
    }
    // --- bias(0): second group ---
    {
        int k0 = ktg * 128;
        #pragma unroll
        for (int i = 0; i < 16; i++) {
            int u = tid + i * 256;
            int row = u >> 5, unit = u & 31;
            CP16(base + LGB + row * 528 + unit * 16,
                 abias + ((size_t)b * L_ + q0 + row) * L_ + k0 + unit * 4);
        }
        CP_COMMIT();
    }

    int wm = wid >> 2, wn = wid & 3;
    int a_row_l = lane & 15;
    int a_cb_l  = (lane >> 4) << 4;
    int b_row_l = lane & 7;
    int b_cb_l  = ((lane >> 3) & 1) << 4;
    int r0 = lane >> 2;
    int c0 = (lane & 3) * 2;
    float* smax = (float*)(smem + LGS);
    float* ssum = smax + 512;
    size_t attn_base = (size_t)bh * L_ * L_;

    for (int t = 0; t < 4; t++) {
        CP_WAIT1();                 // K(t)+Q ready (bias(t) may be in flight)
        __syncthreads();
        if (t < 3) {                // prefetch K(t+1) into the other buffer
            int k0 = (ktg + t + 1) * 128;
            uint32_t kb = base + (((t + 1) & 1) ? LGK1 : LGK0);
            const char* sKh = (const char*)(g_kh + ((size_t)bh * L_ + k0) * HD_);
            const char* sKl = (const char*)(g_kl + ((size_t)bh * L_ + k0) * HD_);
            #pragma unroll
            for (int i = 0; i < 4; i++) {
                int u = tid + i * 256;
                uint32_t off = (uint32_t)u * 16u, sw = sw128(off);
                CP16(kb + sw,         sKh + off);
                CP16(kb + 16384 + sw, sKl + off);
            }
            CP_COMMIT();
        }

        uint32_t kbuf = base + ((t & 1) ? LGK1 : LGK0);
        float acc[4][4][4] = {};

        #pragma unroll
        for (int pass = 0; pass < 3; pass++) {
            uint32_t aBase = base + LGQ + ((pass == 2) ? 16384 : 0);
            uint32_t bBase = kbuf + ((pass == 1) ? 16384 : 0);
            #pragma unroll
            for (int ks = 0; ks < 4; ks++) {
                uint32_t a[4][4];
                #pragma unroll
                for (int mf = 0; mf < 4; mf++) {
                    int row = wm * 64 + mf * 16 + a_row_l;
                    uint32_t addr = aBase + sw128((uint32_t)(row * 128 + ks * 32 + a_cb_l));
                    LDSM_X4(a[mf][0], a[mf][1], a[mf][2], a[mf][3], addr);
                }
                uint32_t bfr[4][2];
                #pragma unroll
                for (int nf = 0; nf < 4; nf++) {
                    int row = wn * 32 + nf * 8 + b_row_l;
                    uint32_t addr = bBase + sw128((uint32_t)(row * 128 + ks * 32 + b_cb_l));
                    LDSM_X2(bfr[nf][0], bfr[nf][1], addr);
                }
                #pragma unroll
                for (int mf = 0; mf < 4; mf++)
                    #pragma unroll
                    for (int nf = 0; nf < 4; nf++)
                        MMA16816(acc[mf][nf], a[mf], bfr[nf]);
            }
        }

        // bias(t) ready (it's the oldest remaining group when t<3; only group at t=3)
        if (t < 3) { CP_WAIT1(); } else { CP_WAIT0(); }
        __syncthreads();

        // epilogue: scale + bias(SMEM) -> acc, write attn
        int k0 = (ktg + t) * 128;
        #pragma unroll
        for (int mf = 0; mf < 4; mf++) {
            #pragma unroll
            for (int e2 = 0; e2 < 2; e2++) {
                int rw = wm * 64 + mf * 16 + e2 * 8 + r0;
                const float* brow = (const float*)(smem + LGB + rw * 528);
                float* orow = attn + attn_base + (size_t)(q0 + rw) * L_ + k0;
                #pragma unroll
                for (int nf = 0; nf < 4; nf++) {
                    int kl = wn * 32 + nf * 8 + c0;
                    float v0 = acc[mf][nf][e2*2+0] * 0.125f + brow[kl];
                    float v1 = acc[mf][nf][e2*2+1] * 0.125f + brow[kl+1];
                    acc[mf][nf][e2*2+0] = v0;
                    acc[mf][nf][e2*2+1] = v1;
                    *(float2*)(orow + kl) = make_float2(v0, v1);
                }
            }
        }

        // per-tile softmax stats
        __syncthreads();   // also: all bias reads done before bias(t+1) issue below
        #pragma unroll
        for (int mf = 0; mf < 4; mf++) {
            #pragma unroll
            for (int e2 = 0; e2 < 2; e2++) {
                float rm = -3.4e38f;
                #pragma unroll
                for (int nf = 0; nf < 4; nf++)
                    rm = fmaxf(rm, fmaxf(acc[mf][nf][e2*2], acc[mf][nf][e2*2+1]));
                rm = fmaxf(rm, __shfl_xor_sync(~0u, rm, 1));
                rm = fmaxf(rm, __shfl_xor_sync(~0u, rm, 2));
                int rw = wm * 64 + mf * 16 + e2 * 8 + r0;
                if ((lane & 3) == 0) smax[rw * 4 + wn] = rm;
            }
        }
        __syncthreads();
        #pragma unroll
        for (int mf = 0; mf < 4; mf++) {
            #pragma unroll
            for (int e2 = 0; e2 < 2; e2++) {
                int rw = wm * 64 + mf * 16 + e2 * 8 + r0;
                float tm = fmaxf(fmaxf(smax[rw*4+0], smax[rw*4+1]),
                                 fmaxf(smax[rw*4+2], smax[rw*4+3]));
                float s = 0.f;
                #pragma unroll
                for (int nf = 0; nf < 4; nf++)
                    s += __expf(acc[mf][nf][e2*2] - tm) + __expf(acc[mf][nf][e2*2+1] - tm);
                s += __shfl_xor_sync(~0u, s, 1);
                s += __shfl_xor_sync(~0u, s, 2);
                if ((lane & 3) == 0) ssum[rw * 4 + wn] = s;
            }
        }
        __syncthreads();
        if (tid < 128) {
            float tm = fmaxf(fmaxf(smax[tid*4+0], smax[tid*4+1]),
                             fmaxf(smax[tid*4+2], smax[tid*4+3]));
            float s = ssum[tid*4+0] + ssum[tid*4+1] + ssum[tid*4+2] + ssum[tid*4+3];
            size_t sidx = ((size_t)bh * L_ + q0 + tid) * KT_ + ktg + t;
            g_pmax[sidx] = tm;
            g_psum[sidx] = s;
        }
        __syncthreads();

        if (t < 3) {   // prefetch bias(t+1) (buffer free now)
            int nk0 = (ktg + t + 1) * 128;
            #pragma unroll
            for (int i = 0; i < 16; i++) {
                int u = tid + i * 256;
                int row = u >> 5, unit = u & 31;
                CP16(base + LGB + row * 528 + unit * 16,
                     abias + ((size_t)b * L_ + q0 + row) * L_ + nk0 + unit * 4);
            }
            CP_COMMIT();
        }
    }
}

// ---------------------------------------------------------------------------
__global__ void combine_stats()
{
    int row = blockIdx.x * 256 + threadIdx.x;
    const float* pm = g_pmax + (size_t)row * KT_;
    const float* ps = g_psum + (size_t)row * KT_;
    float M = -3.4e38f;
    #pragma unroll
    for (int t = 0; t < KT_; t++) M = fmaxf(M, pm[t]);
    float S = 0.f;
    #pragma unroll
    for (int t = 0; t < KT_; t++) S += ps[t] * __expf(pm[t] - M);
    g_rm[row] = M;
    g_ri[row] = 1.0f / S;
}

// ---------------------------------------------------------------------------
// av_fused (unchanged from R7)
// ---------------------------------------------------------------------------
#define AV_BUF  49152
#define AV_SMEM (2 * AV_BUF + 2048)

__global__ void __launch_bounds__(256)
av_fused(float* __restrict__ attn)
{
    extern __shared__ char smem_raw[];
    uint32_t raw = smem_u32(smem_raw);
    uint32_t base = (raw + 1023u) & ~1023u;
    char* smem = smem_raw + (base - raw);

    float* s_m  = (float*)(smem + 2 * AV_BUF);
    float* s_ri = s_m + 128;

    int tid = threadIdx.x;
    int wid = tid >> 5, lane = tid & 31;
    int bh = blockIdx.y;
    int q0 = blockIdx.x * 128;
    int wm = wid >> 1;
    int wn = wid & 1;

    float* A = attn + (size_t)bh * L_ * L_;
    const __nv_bfloat16* Vh = g_vh + (size_t)bh * L_ * HD_;
    const __nv_bfloat16* Vl = g_vl + (size_t)bh * L_ * HD_;

    if (tid < 128) {
        size_t r = (size_t)bh * L_ + q0 + tid;
        s_m[tid]  = g_rm[r];
        s_ri[tid] = g_ri[r];
    }

    int st_row[8], st_f4[8];
    #pragma unroll
    for (int i = 0; i < 8; i++) {
        int u = tid + i * 256;
        st_row[i] = u >> 4;
        st_f4[i]  = (u & 15) * 4;
    }

    auto issueV = [&](int kc, int buf) {
        uint32_t bb = base + (uint32_t)buf * AV_BUF;
        int k0 = kc * 64;
        #pragma unroll
        for (int i = 0; i < 2; i++) {
            int u = tid + i * 256;
            int row = u >> 3, unit = u & 7;
            uint32_t dst = sw128((uint32_t)(row * 128 + unit * 16));
            size_t off = (size_t)(k0 + row) * HD_ + unit * 8;
            CP16(bb + 32768 + dst, Vh + off);
            CP16(bb + 40960 + dst, Vl + off);
        }
        CP_COMMIT();
    };

    float4 apf[8];
    auto loadA = [&](int kc) {
        int k0 = kc * 64;
        #pragma unroll
        for (int i = 0; i < 8; i++)
            apf[i] = *(const float4*)(A + (size_t)(q0 + st_row[i]) * L_ + k0 + st_f4[i]);
    };

    auto xformA = [&](int kc, int buf) {
        char* bb = smem + buf * AV_BUF;
        int k0 = kc * 64;
        #pragma unroll
        for (int i = 0; i < 8; i++) {
            int row = st_row[i], f4 = st_f4[i];
            float m = s_m[row], ri = s_ri[row];
            float4 t = apf[i];
            t.x = __expf(t.x - m) * ri;
            t.y = __expf(t.y - m) * ri;
            t.z = __expf(t.z - m) * ri;
            t.w = __expf(t.w - m) * ri;
            *(float4*)(A + (size_t)(q0 + row) * L_ + k0 + f4) = t;
            float h0 = __bfloat162float(__float2bfloat16(t.x));
            float h1 = __bfloat162float(__float2bfloat16(t.y));
            float h2 = __bfloat162float(__float2bfloat16(t.z));
            float h3 = __bfloat162float(__float2bfloat16(t.w));
            uint32_t so = sw128((uint32_t)(row * 128 + f4 * 2));
            *(uint2*)(bb + so)         = make_uint2(pack_bf2(t.x, t.y), pack_bf2(t.z, t.w));
            *(uint2*)(bb + 16384 + so) = make_uint2(pack_bf2(t.x - h0, t.y - h1),
                                                    pack_bf2(t.z - h2, t.w - h3));
        }
    };

    float acc[2][4][4] = {};
    int a_row_l = lane & 15;
    int a_cb_l  = (lane >> 4) << 4;

    issueV(0, 0);
    loadA(0);
    __syncthreads();
    xformA(0, 0);

    for (int kc = 0; kc < 32; kc++) {
        CP_WAIT0();
        __syncthreads();
        int nb = (kc + 1) & 1;
        if (kc + 1 < 32) {
            issueV(kc + 1, nb);
            loadA(kc + 1);
        }

        uint32_t bb = base + (uint32_t)(kc & 1) * AV_BUF;
        uint32_t aAh = bb, aAl = bb + 16384, aVh = bb + 32768, aVl = bb + 40960;

        #pragma unroll
        for (int ks = 0; ks < 4; ks++) {
            uint32_t a[2][4], bh2[4][2], bl2[4][2];
            #pragma unroll
            for (int mf = 0; mf < 2; mf++) {
                int row = wm * 32 + mf * 16 + a_row_l;
                uint32_t addr = aAh + sw128((uint32_t)(row * 128 + ks * 32 + a_cb_l));
                LDSM_X4(a[mf][0], a[mf][1], a[mf][2], a[mf][3], addr);
            }
            #pragma unroll
            for (int nf = 0; nf < 4; nf++) {
                int row = ks * 16 + (lane & 15);
                uint32_t boff = sw128((uint32_t)(row * 128 + wn * 64 + nf * 16));
                LDSM_X2T(bh2[nf][0], bh2[nf][1], aVh + boff);
                LDSM_X2T(bl2[nf][0], bl2[nf][1], aVl + boff);
            }
            #pragma unroll
            for (int mf = 0; mf < 2; mf++)
                #pragma unroll
                for (int nf = 0; nf < 4; nf++) {
                    MMA16816(acc[mf][nf], a[mf], bh2[nf]);
                    MMA16816(acc[mf][nf], a[mf], bl2[nf]);
                }
            #pragma unroll
            for (int mf = 0; mf < 2; mf++) {
                int row = wm * 32 + mf * 16 + a_row_l;
                uint32_t addr = aAl + sw128((uint32_t)(row * 128 + ks * 32 + a_cb_l));
                LDSM_X4(a[mf][0], a[mf][1], a[mf][2], a[mf][3], addr);
            }
            #pragma unroll
            for (int mf = 0; mf < 2; mf++)
                #pragma unroll
                for (int nf = 0; nf < 4; nf++)
                    MMA16816(acc[mf][nf], a[mf], bh2[nf]);
        }

        if (kc + 1 < 32) xformA(kc + 1, nb);
        __syncthreads();
    }

    int b = bh >> 4, h = bh & 15;
    int r0 = lane >> 2;
    int c0 = (lane & 3) * 2;

    #pragma unroll
    for (int mf = 0; mf < 2; mf++) {
        #pragma unroll
        for (int e2 = 0; e2 < 2; e2++) {
            int q = q0 + wm * 32 + mf * 16 + r0 + e2 * 8;
            #pragma unroll
            for (int nf = 0; nf < 4; nf++) {
                int hd = wn * 32 + nf * 8 + c0;
                float v0 = acc[mf][nf][e2*2+0];
                float v1 = acc[mf][nf][e2*2+1];
                float h0 = __bfloat162float(__float2bfloat16(v0));
                float h1 = __bfloat162float(__float2bfloat16(v1));
                size_t idx = ((size_t)(b * L_ + q)) * D_ + h * HD_ + hd;
                *(uint32_t*)(g_xh + idx) = pack_bf2(v0, v1);
                *(uint32_t*)(g_xl + idx) = pack_bf2(v0 - h0, v1 - h1);
            }
        }
    }
}

// ---------------------------------------------------------------------------
extern "C" void kernel_launch(void* const* d_in, const int* in_sizes, int n_in,
                              void* d_out, int out_size)
{
    const float* query = (const float*)d_in[0];
    const float* abias = (const float*)d_in[1];
    const float* Wq    = (const float*)d_in[2];
    const float* bq    = (const float*)d_in[3];
    const float* Wk    = (const float*)d_in[4];
    const float* bk    = (const float*)d_in[5];
    const float* Wv    = (const float*)d_in[6];
    const float* bv    = (const float*)d_in[7];
    const float* Wo    = (const float*)d_in[8];
    const float* bo    = (const float*)d_in[9];

    float* out  = (float*)d_out;
    float* ans  = out;
    float* attn = out + (size_t)M_ * D_;

    cudaFuncSetAttribute(logits_mma, cudaFuncAttributeMaxDynamicSharedMemorySize, LG_SMEM);
    cudaFuncSetAttribute(qkv_mma,    cudaFuncAttributeMaxDynamicSharedMemorySize, PJ_SMEM);
    cudaFuncSetAttribute(oproj_mma,  cudaFuncAttributeMaxDynamicSharedMemorySize, PJ_SMEM);
    cudaFuncSetAttribute(av_fused,   cudaFuncAttributeMaxDynamicSharedMemorySize, AV_SMEM);

    __nv_bfloat16 *p_inh, *p_inl, *p_wth, *p_wtl, *p_xh, *p_xl;
    cudaGetSymbolAddress((void**)&p_inh, g_inh);
    cudaGetSymbolAddress((void**)&p_inl, g_inl);
    cudaGetSymbolAddress((void**)&p_wth, g_wth);
    cudaGetSymbolAddress((void**)&p_wtl, g_wtl);
    cudaGetSymbolAddress((void**)&p_xh, g_xh);
    cudaGetSymbolAddress((void**)&p_xl, g_xl);

    split_x<<<M_ * D_ / 1024, 256>>>(query);
    split_wt<<<dim3(D_ / 64, D_ / 64, 4), 256>>>(Wq, Wk, Wv, Wo);

    qkv_mma<<<dim3(D_ / 128, M_ / 128, 3), 256, PJ_SMEM>>>(
        p_inh, p_inl, p_wth, p_wtl, bq, bk, bv);

    logits_mma<<<dim3(KT_ / 4, L_ / 128, NBH), 256, LG_SMEM>>>(abias, attn);

    combine_stats<<<NBH * L_ / 256, 256>>>();

    av_fused<<<dim3(L_ / 128, B_ * H_), 256, AV_SMEM>>>(attn);

    oproj_mma<<<dim3(D_ / 128, M_ / 128), 256, PJ_SMEM>>>(
        p_xh, p_xl, p_wth + 3 * (size_t)D_ * D_, p_wtl + 3 * (size_t)D_ * D_, bo, ans);
}